// round 14
// baseline (speedup 1.0000x reference)
#include <cuda_runtime.h>
#include <cuda_bf16.h>
#include <cuda_fp16.h>
#include <mma.h>
#include <cstdint>

using namespace nvcuda;

// ---------------- problem constants ----------------
#define Bc   256
#define Nn   196
#define Hh   8
#define KDc  32
#define VDc  64
#define Qq   49
#define EPSc 1e-5f
#define SCALEc 0.17677669529663689f  // 32^-0.5

// ---------------- device scratch (all fp16) ----------------
__device__ __half g_xh[Bc*Nn*256];                     // x fp16
__device__ __half g_kwf[256*256];                      // kv_w K-part, reordered
__device__ __half g_vwf[512*256];                      // kv_w V-part, reordered
__device__ __half g_qwf[256*256];                      // q_w
__device__ __half g_pwf[384*512];                      // proj W (inv-scaled)
__device__ __half g_af[Bc*Qq*512];                     // attn out
__device__ __half g_kf[Bc*Hh*Nn*KDc];                  // [bh,n,d]
__device__ __half g_vf[Bc*Hh*Nn*VDc];                  // [bh,n,d]
__device__ __half g_qf[Bc*Hh*Qq*KDc];                  // [bh,q,d] (SCALEc folded)

// ---------------- cp.async helpers ----------------
__device__ __forceinline__ void cp16(uint32_t dst, const void* src) {
    asm volatile("cp.async.cg.shared.global [%0], [%1], 16;" :: "r"(dst), "l"(src));
}
#define CP_COMMIT() asm volatile("cp.async.commit_group;" ::: "memory")
#define CP_WAIT0()  asm volatile("cp.async.wait_group 0;" ::: "memory")

__device__ __forceinline__ uint32_t smem_u32(const void* p) {
    uint32_t a;
    asm("{ .reg .u64 t; cvta.to.shared.u64 t, %1; cvt.u32.u64 %0, t; }" : "=r"(a) : "l"(p));
    return a;
}

// ---------------- fused precompute (all fp16 converts) ----------------
#define NX  (Bc*Nn*256/4)
#define NW1 (768*256/4)
#define NW2 (256*256/4)
#define NW3 (384*512/4)
__global__ void split_all_kernel(const float* __restrict__ x,
                                 const float* __restrict__ kv_w,
                                 const float* __restrict__ q_w,
                                 const float* __restrict__ proj_w,
                                 const float* __restrict__ proj_g,
                                 const float* __restrict__ proj_v)
{
    int i = blockIdx.x * blockDim.x + threadIdx.x;
    if (i < NX) {
        float4 t = reinterpret_cast<const float4*>(x)[i];
        reinterpret_cast<__half2*>(g_xh)[i*2]   = __floats2half2_rn(t.x, t.y);
        reinterpret_cast<__half2*>(g_xh)[i*2+1] = __floats2half2_rn(t.z, t.w);
    } else if (i < NX + NW1) {
        int j = i - NX;
        int r = j >> 6, c4 = j & 63;
        float4 t = reinterpret_cast<const float4*>(kv_w)[j];
        int h = r / 96, c = r - h * 96;
        int di;
        __half* dst;
        if (c < KDc) { di = (h * 32 + c) * 64 + c4;          dst = g_kwf; }
        else         { di = (h * 64 + (c - KDc)) * 64 + c4;  dst = g_vwf; }
        reinterpret_cast<__half2*>(dst)[di*2]   = __floats2half2_rn(t.x, t.y);
        reinterpret_cast<__half2*>(dst)[di*2+1] = __floats2half2_rn(t.z, t.w);
    } else if (i < NX + NW1 + NW2) {
        int j = i - NX - NW1;
        float4 t = reinterpret_cast<const float4*>(q_w)[j];
        reinterpret_cast<__half2*>(g_qwf)[j*2]   = __floats2half2_rn(t.x, t.y);
        reinterpret_cast<__half2*>(g_qwf)[j*2+1] = __floats2half2_rn(t.z, t.w);
    } else if (i < NX + NW1 + NW2 + NW3) {
        int j = i - NX - NW1 - NW2;
        int row = j >> 7;
        float inv = proj_g[row] * rsqrtf(proj_v[row] + EPSc);
        float4 t = reinterpret_cast<const float4*>(proj_w)[j];
        t.x *= inv; t.y *= inv; t.z *= inv; t.w *= inv;
        reinterpret_cast<__half2*>(g_pwf)[j*2]   = __floats2half2_rn(t.x, t.y);
        reinterpret_cast<__half2*>(g_pwf)[j*2+1] = __floats2half2_rn(t.z, t.w);
    }
}

// ---------------- GEMM smem layout ----------------
#define TSTRIDE 40
#define OFF_ROW   64
#define OFF_INV   576
#define OFF_SH    1088
#define OFF_TILES 2048
#define STAGE_BYTES 20480      // Ah | Wf
#define OFF_STAGE 2048
#define SSTRIDE   132
#define GEMM_SMEM_BYTES 69632

#define KB 784
#define VB 2352
#define TOTAL_B 2548

// ---------------------------------------------------------------------------
// Fused K/V/q GEMM, uniform single-term fp16, 512 threads, 32x32 warp tiles.
// ---------------------------------------------------------------------------
__global__ __launch_bounds__(512, 2)
void kvq_gemm_kernel(const float* __restrict__ kv_g, const float* __restrict__ kv_b,
                     const float* __restrict__ kv_m, const float* __restrict__ kv_v,
                     const float* __restrict__ q_g,  const float* __restrict__ q_b,
                     const float* __restrict__ q_m,  const float* __restrict__ q_v)
{
    extern __shared__ char sm[];
    const uint32_t sb = smem_u32(sm);
    int*   rowoff = (int*)(sm + OFF_ROW);
    float* sInv   = (float*)(sm + OFF_INV);
    float* sSh    = (float*)(sm + OFF_SH);
    float* S      = (float*)(sm + OFF_STAGE);

    const int bx = blockIdx.x;
    int mode, n0, m0;
    if (bx < KB)      { mode = 0; n0 = (bx & 1) * 128;  m0 = (bx >> 1) * 128; }
    else if (bx < VB) { int i = bx - KB; mode = 1; n0 = (i & 3) * 128; m0 = (i >> 2) * 128; }
    else              { int i = bx - VB; mode = 2; n0 = (i & 1) * 128; m0 = (i >> 1) * 128; }

    const __half* Wf = (mode == 0) ? g_kwf : (mode == 1) ? g_vwf : g_qwf;

    const int tid = threadIdx.x;
    const int wid = tid >> 5;

    if (tid < 128) {
        int m = m0 + tid;
        int off;
        if (mode == 2) {
            int b = m / Qq, qq = m % Qq;
            int n = (qq / 7) * 28 + (qq % 7) * 2;
            off = (b * Nn + n) * 256;
        } else {
            off = m * 256;
        }
        rowoff[tid] = off;
        int jj = n0 + tid;
        int jo;
        const float *gg, *bb, *mm, *vv;
        if (mode == 0)      { jo = (jj >> 5) * 96 + (jj & 31);        gg = kv_g; bb = kv_b; mm = kv_m; vv = kv_v; }
        else if (mode == 1) { jo = (jj >> 6) * 96 + KDc + (jj & 63);  gg = kv_g; bb = kv_b; mm = kv_m; vv = kv_v; }
        else                { jo = jj;                                 gg = q_g;  bb = q_b;  mm = q_m;  vv = q_v;  }
        float inv = gg[jo] * rsqrtf(vv[jo] + EPSc);
        float sh  = bb[jo] - mm[jo] * inv;
        if (mode == 2) { inv *= SCALEc; sh *= SCALEc; }
        sInv[tid] = inv;
        sSh[tid]  = sh;
    }
    __syncthreads();

    const int r = tid >> 2, k8 = (tid & 3) * 8;
    const int aoff = rowoff[r] + k8;
    const int woff = (n0 + r) * 256 + k8;
    const uint32_t so = (uint32_t)(r * TSTRIDE + k8) * 2;

    const int wm0 = (wid & 3) * 32;
    const int wn0 = (wid >> 2) * 32;

    wmma::fragment<wmma::accumulator, 16, 16, 16, float> acc[2][2];
#pragma unroll
    for (int i = 0; i < 2; i++)
#pragma unroll
        for (int j = 0; j < 2; j++) wmma::fill_fragment(acc[i][j], 0.0f);

    auto load1 = [&](int c, int stage) {
        const uint32_t base = sb + OFF_TILES + stage * STAGE_BYTES;
        const int k0 = c * 32;
        cp16(base + so,         g_xh + aoff + k0);
        cp16(base + 10240 + so, Wf + woff + k0);
        CP_COMMIT();
    };
    load1(0, 0);

#pragma unroll 1
    for (int c = 0; c < 8; c++) {
        CP_WAIT0();
        __syncthreads();
        if (c + 1 < 8) load1(c + 1, (c + 1) & 1);
        char* st = sm + OFF_TILES + (c & 1) * STAGE_BYTES;
        __half* Ahs = (__half*)(st);
        __half* Wfs = (__half*)(st + 10240);
#pragma unroll
        for (int kk = 0; kk < 32; kk += 16) {
#pragma unroll
            for (int j = 0; j < 2; j++) {
                wmma::fragment<wmma::matrix_b, 16, 16, 16, __half, wmma::col_major> bf;
                wmma::load_matrix_sync(bf, Wfs + (wn0 + j * 16) * TSTRIDE + kk, TSTRIDE);
#pragma unroll
                for (int i = 0; i < 2; i++) {
                    wmma::fragment<wmma::matrix_a, 16, 16, 16, __half, wmma::row_major> af;
                    wmma::load_matrix_sync(af, Ahs + (wm0 + i * 16) * TSTRIDE + kk, TSTRIDE);
                    wmma::mma_sync(acc[i][j], af, bf, acc[i][j]);
                }
            }
        }
        __syncthreads();
    }

#pragma unroll
    for (int i = 0; i < 2; i++)
#pragma unroll
        for (int j = 0; j < 2; j++)
            wmma::store_matrix_sync(S + (wm0 + i * 16) * SSTRIDE + wn0 + j * 16,
                                    acc[i][j], SSTRIDE, wmma::mem_row_major);
    __syncthreads();

    for (int idx = tid; idx < 8192; idx += 512) {
        int mrow = idx >> 6, pair = idx & 63, col = pair * 2;
        int jj = n0 + col;
        int m = m0 + mrow;
        float v0 = S[mrow * SSTRIDE + col]     * sInv[col]     + sSh[col];
        float v1 = S[mrow * SSTRIDE + col + 1] * sInv[col + 1] + sSh[col + 1];
        __half2 hv = __floats2half2_rn(v0, v1);
        if (mode == 0) {
            int h = jj >> 5, d = jj & 31;
            int b = m / Nn, n = m - b * Nn;
            *reinterpret_cast<__half2*>(g_kf + ((size_t)((b * Hh + h) * Nn + n)) * KDc + d) = hv;
        } else if (mode == 1) {
            int h = jj >> 6, d = jj & 63;
            int b = m / Nn, n = m - b * Nn;
            *reinterpret_cast<__half2*>(g_vf + ((size_t)((b * Hh + h) * Nn + n)) * VDc + d) = hv;
        } else {
            int h = jj >> 5, d = jj & 31;
            int b = m / Qq, qq = m - b * Qq;
            *reinterpret_cast<__half2*>(g_qf + ((size_t)((b * Hh + h) * Qq + qq)) * KDc + d) = hv;
        }
    }
}

// ---------------------------------------------------------------------------
// proj GEMM: single-term fp16, 512 threads, 32x32 warp tiles.
// ---------------------------------------------------------------------------
#define P_STAGE_BYTES 20480
#define PGEMM_SMEM_BYTES 69632

__global__ __launch_bounds__(512, 2)
void pgemm_kernel(const float* __restrict__ gg,
                  const float* __restrict__ bb,
                  const float* __restrict__ mm,
                  const float* __restrict__ vv,
                  float* __restrict__ Out)
{
    extern __shared__ char sm[];
    const uint32_t sb = smem_u32(sm);
    float* sSh  = (float*)(sm + OFF_SH);
    float* S    = (float*)(sm + OFF_STAGE);

    const int tid = threadIdx.x;
    const int wid = tid >> 5;
    const int m0 = blockIdx.y * 128;
    const int n0 = blockIdx.x * 128;

    if (tid < 128) {
        int jj = n0 + tid;
        float inv = gg[jj] * rsqrtf(vv[jj] + EPSc);
        sSh[tid]  = bb[jj] - mm[jj] * inv;
    }
    __syncthreads();

    const int r = tid >> 2, k8 = (tid & 3) * 8;
    const int aoff = (m0 + r) * 512 + k8;
    const int woff = (n0 + r) * 512 + k8;
    const uint32_t so = (uint32_t)(r * TSTRIDE + k8) * 2;

    const int wm0 = (wid & 3) * 32;
    const int wn0 = (wid >> 2) * 32;

    wmma::fragment<wmma::accumulator, 16, 16, 16, float> acc[2][2];
#pragma unroll
    for (int i = 0; i < 2; i++)
#pragma unroll
        for (int j = 0; j < 2; j++) wmma::fill_fragment(acc[i][j], 0.0f);

    auto load_chunk = [&](int c, int stage) {
        const uint32_t base = sb + OFF_TILES + stage * P_STAGE_BYTES;
        const int k0 = c * 32;
        cp16(base + so,         g_af + aoff + k0);
        cp16(base + 10240 + so, g_pwf + woff + k0);
        CP_COMMIT();
    };

    load_chunk(0, 0);

#pragma unroll 1
    for (int c = 0; c < 16; c++) {
        CP_WAIT0();
        __syncthreads();
        if (c + 1 < 16) load_chunk(c + 1, (c + 1) & 1);

        char* st = sm + OFF_TILES + (c & 1) * P_STAGE_BYTES;
        __half* Afs = (__half*)(st);
        __half* Wfs = (__half*)(st + 10240);

#pragma unroll
        for (int kk = 0; kk < 32; kk += 16) {
#pragma unroll
            for (int j = 0; j < 2; j++) {
                wmma::fragment<wmma::matrix_b, 16, 16, 16, __half, wmma::col_major> bf;
                wmma::load_matrix_sync(bf, Wfs + (wn0 + j * 16) * TSTRIDE + kk, TSTRIDE);
#pragma unroll
                for (int i = 0; i < 2; i++) {
                    wmma::fragment<wmma::matrix_a, 16, 16, 16, __half, wmma::row_major> af;
                    wmma::load_matrix_sync(af, Afs + (wm0 + i * 16) * TSTRIDE + kk, TSTRIDE);
                    wmma::mma_sync(acc[i][j], af, bf, acc[i][j]);
                }
            }
        }
        __syncthreads();
    }

#pragma unroll
    for (int i = 0; i < 2; i++)
#pragma unroll
        for (int j = 0; j < 2; j++)
            wmma::store_matrix_sync(S + (wm0 + i * 16) * SSTRIDE + wn0 + j * 16,
                                    acc[i][j], SSTRIDE, wmma::mem_row_major);
    __syncthreads();

    for (int idx = tid; idx < 4096; idx += 512) {
        int mrow = idx >> 5, col = (idx & 31) * 4;
        float4 o;
        o.x = S[mrow * SSTRIDE + col + 0] + sSh[col + 0];
        o.y = S[mrow * SSTRIDE + col + 1] + sSh[col + 1];
        o.z = S[mrow * SSTRIDE + col + 2] + sSh[col + 2];
        o.w = S[mrow * SSTRIDE + col + 3] + sSh[col + 3];
        *reinterpret_cast<float4*>(Out + (size_t)(m0 + mrow) * 384 + n0 + col) = o;
    }
}

// ---------------------------------------------------------------------------
// Attention: one block per (b,h), 512 threads, single-fp16 q/k, 1-term scores.
// smem: bias | sc fp32 [64][212] | X{ qf[64][40]+kf[208][40] | Ph[64][216]+Vh[208][72] }
// ---------------------------------------------------------------------------
#define AT_BIAS 0
#define AT_SC   832
#define AT_X    55104
#define AT_QF   (AT_X)
#define AT_KF   (AT_X + 5120)
#define AT_PH   (AT_X)
#define AT_VH   (AT_X + 27648)
#define ATTN_SMEM_BYTES 112704

__global__ __launch_bounds__(512, 2)
void attn_kernel(const float* __restrict__ attn_bias)
{
    extern __shared__ char smc[];
    const uint32_t sb = smem_u32(smc);
    float* bs = (float*)(smc + AT_BIAS);
    float* sc = (float*)(smc + AT_SC);                      // [64][212]
    __half* qf = (__half*)(smc + AT_QF);                    // [64][40]
    __half* kf = (__half*)(smc + AT_KF);                    // [208][40]
    __half* Ph = (__half*)(smc + AT_PH);                    // [64][216]
    __half* Vh = (__half*)(smc + AT_VH);                    // [208][72]

    const int blk = blockIdx.x;           // b*8 + h
    const int h = blk & 7;
    const int tid = threadIdx.x;
    const int wid = tid >> 5, lane = tid & 31;

    // phase 0: load q, k (fp16); zero pads; bias
    {
        const uint4* qg = (const uint4*)(g_qf + (size_t)blk * (Qq * KDc));
        for (int i = tid; i < 196; i += 512) {
            cp16(sb + AT_QF + (i >> 2) * 80 + (i & 3) * 16, qg + i);
        }
        const uint4* kg = (const uint4*)(g_kf + (size_t)blk * (Nn * KDc));
        for (int i = tid; i < 784; i += 512) {
            cp16(sb + AT_KF + (i >> 2) * 80 + (i & 3) * 16, kg + i);
        }
        CP_COMMIT();
        uint4 z = {0u, 0u, 0u, 0u};
        for (int i = tid; i < 75; i += 512) {
            int row = 49 + i / 5, seg = i % 5;
            *(uint4*)(smc + AT_QF + row * 80 + seg * 16) = z;
        }
        for (int i = tid; i < 60; i += 512) {
            int row = 196 + i / 5, seg = i % 5;
            *(uint4*)(smc + AT_KF + row * 80 + seg * 16) = z;
        }
        for (int i = tid; i < 196; i += 512) bs[i] = attn_bias[h * Nn + i];
        CP_WAIT0();
    }
    __syncthreads();

    // phase 1: scores = qf @ kf^T (1 term); 13 warps x 16-col strip
    if (wid < 13) {
        const int n0 = wid * 16;
        wmma::fragment<wmma::accumulator, 16, 16, 16, float> acc[4];
#pragma unroll
        for (int mt = 0; mt < 4; mt++) wmma::fill_fragment(acc[mt], 0.0f);
#pragma unroll
        for (int kk = 0; kk < 2; kk++) {
            wmma::fragment<wmma::matrix_b, 16, 16, 16, __half, wmma::col_major> bf;
            wmma::load_matrix_sync(bf, kf + n0 * 40 + kk * 16, 40);
#pragma unroll
            for (int mt = 0; mt < 4; mt++) {
                wmma::fragment<wmma::matrix_a, 16, 16, 16, __half, wmma::row_major> af;
                wmma::load_matrix_sync(af, qf + mt * 16 * 40 + kk * 16, 40);
                wmma::mma_sync(acc[mt], af, bf, acc[mt]);
            }
        }
#pragma unroll
        for (int mt = 0; mt < 4; mt++)
            wmma::store_matrix_sync(sc + mt * 16 * 212 + n0, acc[mt], 212, wmma::mem_row_major);
    }
    __syncthreads();

    // phase 2: prefetch V (fp16); zero pad rows + Ph pad rows
    {
        const uint4* vfg = (const uint4*)(g_vf + (size_t)blk * (Nn * VDc));
        for (int i = tid; i < 1568; i += 512) {
            cp16(sb + AT_VH + (i >> 3) * 144 + (i & 7) * 16, vfg + i);
        }
        CP_COMMIT();
        uint4 z = {0u, 0u, 0u, 0u};
        for (int i = tid; i < 108; i += 512) {
            int row = 196 + i / 9, seg = i % 9;
            *(uint4*)(smc + AT_VH + row * 144 + seg * 16) = z;
        }
        for (int i = tid; i < 405; i += 512) {
            int row = 49 + i / 27, seg = i % 27;
            *(uint4*)(smc + AT_PH + row * 432 + seg * 16) = z;
        }
    }

    // phase 3: softmax (fp32) -> Ph fp16 (SCALEc folded into q)
    for (int row = wid; row < Qq; row += 16) {
        int qi2 = 2 * (row / 7), qj2 = 2 * (row % 7);
        float mx = -1e30f;
        for (int n = lane; n < Nn; n += 32) {
            int ki = n / 14, kj = n - ki * 14;
            float val = sc[row * 212 + n] + bs[abs(qi2 - ki) * 14 + abs(qj2 - kj)];
            sc[row * 212 + n] = val;
            mx = fmaxf(mx, val);
        }
#pragma unroll
        for (int o = 16; o > 0; o >>= 1)
            mx = fmaxf(mx, __shfl_xor_sync(0xffffffffu, mx, o));
        float sum = 0.0f;
        for (int n = lane; n < Nn; n += 32) {
            float e = __expf(sc[row * 212 + n] - mx);
            sc[row * 212 + n] = e;
            sum += e;
        }
#pragma unroll
        for (int o = 16; o > 0; o >>= 1)
            sum += __shfl_xor_sync(0xffffffffu, sum, o);
        float rinv = 1.0f / sum;
        for (int n = lane; n < 208; n += 32) {
            float p = (n < Nn) ? sc[row * 212 + n] * rinv : 0.0f;
            Ph[row * 216 + n] = __float2half_rn(p);
        }
    }
    CP_WAIT0();
    __syncthreads();

    // phase 4: AV = Ph @ Vh; 16 warps, one 16x16 tile each
    {
        const int mi = wid >> 2, ni = wid & 3;
        wmma::fragment<wmma::accumulator, 16, 16, 16, float> acc;
        wmma::fill_fragment(acc, 0.0f);
#pragma unroll
        for (int kk = 0; kk < 13; kk++) {
            wmma::fragment<wmma::matrix_a, 16, 16, 16, __half, wmma::row_major> pf;
            wmma::fragment<wmma::matrix_b, 16, 16, 16, __half, wmma::row_major> vf;
            wmma::load_matrix_sync(pf, Ph + mi * 16 * 216 + kk * 16, 216);
            wmma::load_matrix_sync(vf, Vh + kk * 16 * 72 + ni * 16, 72);
            wmma::mma_sync(acc, pf, vf, acc);
        }
        wmma::store_matrix_sync(sc + mi * 16 * 68 + ni * 16, acc, 68, wmma::mem_row_major);
    }
    __syncthreads();

    // phase 5: hardswish + fp16 store to g_af
    {
        const int b = blk >> 3;
        for (int i = tid; i < 1568; i += 512) {
            int qr = i >> 5, vd = (i & 31) * 2;
            float t0 = sc[qr * 68 + vd];
            float t1 = sc[qr * 68 + vd + 1];
            float o0 = t0 * fminf(fmaxf(t0 + 3.0f, 0.0f), 6.0f) * (1.0f / 6.0f);
            float o1 = t1 * fminf(fmaxf(t1 + 3.0f, 0.0f), 6.0f) * (1.0f / 6.0f);
            size_t off = ((size_t)(b * Qq + qr)) * 512 + h * VDc + vd;
            *reinterpret_cast<__half2*>(g_af + off) = __floats2half2_rn(o0, o1);
        }
    }
}

// ---------------------------------------------------------------------------
extern "C" void kernel_launch(void* const* d_in, const int* in_sizes, int n_in,
                              void* d_out, int out_size)
{
    const float* x      = (const float*)d_in[0];
    const float* kv_w   = (const float*)d_in[1];
    const float* kv_g   = (const float*)d_in[2];
    const float* kv_b   = (const float*)d_in[3];
    const float* kv_m   = (const float*)d_in[4];
    const float* kv_v   = (const float*)d_in[5];
    const float* q_w    = (const float*)d_in[6];
    const float* q_g    = (const float*)d_in[7];
    const float* q_b    = (const float*)d_in[8];
    const float* q_m    = (const float*)d_in[9];
    const float* q_v    = (const float*)d_in[10];
    const float* proj_w = (const float*)d_in[11];
    const float* proj_g = (const float*)d_in[12];
    const float* proj_b = (const float*)d_in[13];
    const float* proj_m = (const float*)d_in[14];
    const float* proj_v = (const float*)d_in[15];
    const float* attn_bias = (const float*)d_in[16];
    float* out = (float*)d_out;

    split_all_kernel<<<(NX + NW1 + NW2 + NW3 + 255) / 256, 256>>>(
        x, kv_w, q_w, proj_w, proj_g, proj_v);

    cudaFuncSetAttribute(kvq_gemm_kernel, cudaFuncAttributeMaxDynamicSharedMemorySize, GEMM_SMEM_BYTES);
    cudaFuncSetAttribute(pgemm_kernel, cudaFuncAttributeMaxDynamicSharedMemorySize, PGEMM_SMEM_BYTES);
    cudaFuncSetAttribute(attn_kernel, cudaFuncAttributeMaxDynamicSharedMemorySize, ATTN_SMEM_BYTES);

    kvq_gemm_kernel<<<TOTAL_B, 512, GEMM_SMEM_BYTES>>>(
        kv_g, kv_b, kv_m, kv_v, q_g, q_b, q_m, q_v);

    attn_kernel<<<Bc * Hh, 512, ATTN_SMEM_BYTES>>>(attn_bias);

    pgemm_kernel<<<dim3(3, 98), 512, PGEMM_SMEM_BYTES>>>(proj_g, proj_b, proj_m, proj_v, out);
}

// round 15
// speedup vs baseline: 1.4982x; 1.4982x over previous
#include <cuda_runtime.h>
#include <cuda_bf16.h>
#include <cuda_fp16.h>
#include <mma.h>
#include <cstdint>

using namespace nvcuda;

// ---------------- problem constants ----------------
#define Bc   256
#define Nn   196
#define Hh   8
#define KDc  32
#define VDc  64
#define Qq   49
#define EPSc 1e-5f
#define SCALEc 0.17677669529663689f  // 32^-0.5

// ---------------- device scratch (all fp16) ----------------
__device__ __half g_xh[Bc*Nn*256];                     // x fp16
__device__ __half g_kwf[256*256];                      // kv_w K-part, reordered
__device__ __half g_vwf[512*256];                      // kv_w V-part, reordered
__device__ __half g_qwf[256*256];                      // q_w
__device__ __half g_pwf[384*512];                      // proj W (inv-scaled)
__device__ __half g_af[Bc*Qq*512];                     // attn out
__device__ __half g_kf[Bc*Hh*Nn*KDc];                  // [bh,n,d]
__device__ __half g_vf[Bc*Hh*Nn*VDc];                  // [bh,n,d]
__device__ __half g_qf[Bc*Hh*Qq*KDc];                  // [bh,q,d] (SCALEc folded)

// ---------------- cp.async helpers ----------------
__device__ __forceinline__ void cp16(uint32_t dst, const void* src) {
    asm volatile("cp.async.cg.shared.global [%0], [%1], 16;" :: "r"(dst), "l"(src));
}
#define CP_COMMIT() asm volatile("cp.async.commit_group;" ::: "memory")
#define CP_WAIT0()  asm volatile("cp.async.wait_group 0;" ::: "memory")
#define CP_WAIT1()  asm volatile("cp.async.wait_group 1;" ::: "memory")

__device__ __forceinline__ uint32_t smem_u32(const void* p) {
    uint32_t a;
    asm("{ .reg .u64 t; cvta.to.shared.u64 t, %1; cvt.u32.u64 %0, t; }" : "=r"(a) : "l"(p));
    return a;
}

// ---------------- fused precompute (all fp16 converts) ----------------
#define NX  (Bc*Nn*256/4)
#define NW1 (768*256/4)
#define NW2 (256*256/4)
#define NW3 (384*512/4)
__global__ void split_all_kernel(const float* __restrict__ x,
                                 const float* __restrict__ kv_w,
                                 const float* __restrict__ q_w,
                                 const float* __restrict__ proj_w,
                                 const float* __restrict__ proj_g,
                                 const float* __restrict__ proj_v)
{
    int i = blockIdx.x * blockDim.x + threadIdx.x;
    if (i < NX) {
        float4 t = reinterpret_cast<const float4*>(x)[i];
        reinterpret_cast<__half2*>(g_xh)[i*2]   = __floats2half2_rn(t.x, t.y);
        reinterpret_cast<__half2*>(g_xh)[i*2+1] = __floats2half2_rn(t.z, t.w);
    } else if (i < NX + NW1) {
        int j = i - NX;
        int r = j >> 6, c4 = j & 63;
        float4 t = reinterpret_cast<const float4*>(kv_w)[j];
        int h = r / 96, c = r - h * 96;
        int di;
        __half* dst;
        if (c < KDc) { di = (h * 32 + c) * 64 + c4;          dst = g_kwf; }
        else         { di = (h * 64 + (c - KDc)) * 64 + c4;  dst = g_vwf; }
        reinterpret_cast<__half2*>(dst)[di*2]   = __floats2half2_rn(t.x, t.y);
        reinterpret_cast<__half2*>(dst)[di*2+1] = __floats2half2_rn(t.z, t.w);
    } else if (i < NX + NW1 + NW2) {
        int j = i - NX - NW1;
        float4 t = reinterpret_cast<const float4*>(q_w)[j];
        reinterpret_cast<__half2*>(g_qwf)[j*2]   = __floats2half2_rn(t.x, t.y);
        reinterpret_cast<__half2*>(g_qwf)[j*2+1] = __floats2half2_rn(t.z, t.w);
    } else if (i < NX + NW1 + NW2 + NW3) {
        int j = i - NX - NW1 - NW2;
        int row = j >> 7;
        float inv = proj_g[row] * rsqrtf(proj_v[row] + EPSc);
        float4 t = reinterpret_cast<const float4*>(proj_w)[j];
        t.x *= inv; t.y *= inv; t.z *= inv; t.w *= inv;
        reinterpret_cast<__half2*>(g_pwf)[j*2]   = __floats2half2_rn(t.x, t.y);
        reinterpret_cast<__half2*>(g_pwf)[j*2+1] = __floats2half2_rn(t.z, t.w);
    }
}

// ---------------- GEMM smem layout ----------------
#define TSTRIDE 40
#define OFF_ROW   64
#define OFF_INV   576
#define OFF_SH    1088
#define OFF_TILES 2048
#define STAGE_BYTES 20480      // Ah | Wf
#define OFF_STAGE 2048
#define SSTRIDE   132
#define GEMM_SMEM_BYTES 69632

#define KB 784
#define VB 2352
#define TOTAL_B 2548

// ---------------------------------------------------------------------------
// Fused K/V/q GEMM, uniform single-term fp16, 512 threads, 32x32 warp tiles.
// ---------------------------------------------------------------------------
__global__ __launch_bounds__(512, 2)
void kvq_gemm_kernel(const float* __restrict__ kv_g, const float* __restrict__ kv_b,
                     const float* __restrict__ kv_m, const float* __restrict__ kv_v,
                     const float* __restrict__ q_g,  const float* __restrict__ q_b,
                     const float* __restrict__ q_m,  const float* __restrict__ q_v)
{
    extern __shared__ char sm[];
    const uint32_t sb = smem_u32(sm);
    int*   rowoff = (int*)(sm + OFF_ROW);
    float* sInv   = (float*)(sm + OFF_INV);
    float* sSh    = (float*)(sm + OFF_SH);
    float* S      = (float*)(sm + OFF_STAGE);

    const int bx = blockIdx.x;
    int mode, n0, m0;
    if (bx < KB)      { mode = 0; n0 = (bx & 1) * 128;  m0 = (bx >> 1) * 128; }
    else if (bx < VB) { int i = bx - KB; mode = 1; n0 = (i & 3) * 128; m0 = (i >> 2) * 128; }
    else              { int i = bx - VB; mode = 2; n0 = (i & 1) * 128; m0 = (i >> 1) * 128; }

    const __half* Wf = (mode == 0) ? g_kwf : (mode == 1) ? g_vwf : g_qwf;

    const int tid = threadIdx.x;
    const int wid = tid >> 5;

    if (tid < 128) {
        int m = m0 + tid;
        int off;
        if (mode == 2) {
            int b = m / Qq, qq = m % Qq;
            int n = (qq / 7) * 28 + (qq % 7) * 2;
            off = (b * Nn + n) * 256;
        } else {
            off = m * 256;
        }
        rowoff[tid] = off;
        int jj = n0 + tid;
        int jo;
        const float *gg, *bb, *mm, *vv;
        if (mode == 0)      { jo = (jj >> 5) * 96 + (jj & 31);        gg = kv_g; bb = kv_b; mm = kv_m; vv = kv_v; }
        else if (mode == 1) { jo = (jj >> 6) * 96 + KDc + (jj & 63);  gg = kv_g; bb = kv_b; mm = kv_m; vv = kv_v; }
        else                { jo = jj;                                 gg = q_g;  bb = q_b;  mm = q_m;  vv = q_v;  }
        float inv = gg[jo] * rsqrtf(vv[jo] + EPSc);
        float sh  = bb[jo] - mm[jo] * inv;
        if (mode == 2) { inv *= SCALEc; sh *= SCALEc; }
        sInv[tid] = inv;
        sSh[tid]  = sh;
    }
    __syncthreads();

    const int r = tid >> 2, k8 = (tid & 3) * 8;
    const int aoff = rowoff[r] + k8;
    const int woff = (n0 + r) * 256 + k8;
    const uint32_t so = (uint32_t)(r * TSTRIDE + k8) * 2;

    const int wm0 = (wid & 3) * 32;
    const int wn0 = (wid >> 2) * 32;

    wmma::fragment<wmma::accumulator, 16, 16, 16, float> acc[2][2];
#pragma unroll
    for (int i = 0; i < 2; i++)
#pragma unroll
        for (int j = 0; j < 2; j++) wmma::fill_fragment(acc[i][j], 0.0f);

    auto load1 = [&](int c, int stage) {
        const uint32_t base = sb + OFF_TILES + stage * STAGE_BYTES;
        const int k0 = c * 32;
        cp16(base + so,         g_xh + aoff + k0);
        cp16(base + 10240 + so, Wf + woff + k0);
        CP_COMMIT();
    };
    load1(0, 0);

#pragma unroll 1
    for (int c = 0; c < 8; c++) {
        CP_WAIT0();
        __syncthreads();
        if (c + 1 < 8) load1(c + 1, (c + 1) & 1);
        char* st = sm + OFF_TILES + (c & 1) * STAGE_BYTES;
        __half* Ahs = (__half*)(st);
        __half* Wfs = (__half*)(st + 10240);
#pragma unroll
        for (int kk = 0; kk < 32; kk += 16) {
#pragma unroll
            for (int j = 0; j < 2; j++) {
                wmma::fragment<wmma::matrix_b, 16, 16, 16, __half, wmma::col_major> bf;
                wmma::load_matrix_sync(bf, Wfs + (wn0 + j * 16) * TSTRIDE + kk, TSTRIDE);
#pragma unroll
                for (int i = 0; i < 2; i++) {
                    wmma::fragment<wmma::matrix_a, 16, 16, 16, __half, wmma::row_major> af;
                    wmma::load_matrix_sync(af, Ahs + (wm0 + i * 16) * TSTRIDE + kk, TSTRIDE);
                    wmma::mma_sync(acc[i][j], af, bf, acc[i][j]);
                }
            }
        }
        __syncthreads();
    }

#pragma unroll
    for (int i = 0; i < 2; i++)
#pragma unroll
        for (int j = 0; j < 2; j++)
            wmma::store_matrix_sync(S + (wm0 + i * 16) * SSTRIDE + wn0 + j * 16,
                                    acc[i][j], SSTRIDE, wmma::mem_row_major);
    __syncthreads();

    for (int idx = tid; idx < 8192; idx += 512) {
        int mrow = idx >> 6, pair = idx & 63, col = pair * 2;
        int jj = n0 + col;
        int m = m0 + mrow;
        float v0 = S[mrow * SSTRIDE + col]     * sInv[col]     + sSh[col];
        float v1 = S[mrow * SSTRIDE + col + 1] * sInv[col + 1] + sSh[col + 1];
        __half2 hv = __floats2half2_rn(v0, v1);
        if (mode == 0) {
            int h = jj >> 5, d = jj & 31;
            int b = m / Nn, n = m - b * Nn;
            *reinterpret_cast<__half2*>(g_kf + ((size_t)((b * Hh + h) * Nn + n)) * KDc + d) = hv;
        } else if (mode == 1) {
            int h = jj >> 6, d = jj & 63;
            int b = m / Nn, n = m - b * Nn;
            *reinterpret_cast<__half2*>(g_vf + ((size_t)((b * Hh + h) * Nn + n)) * VDc + d) = hv;
        } else {
            int h = jj >> 5, d = jj & 31;
            int b = m / Qq, qq = m - b * Qq;
            *reinterpret_cast<__half2*>(g_qf + ((size_t)((b * Hh + h) * Qq + qq)) * KDc + d) = hv;
        }
    }
}

// ---------------------------------------------------------------------------
// proj GEMM: single-term fp16, 512 threads, 32x32 warp tiles.
// ---------------------------------------------------------------------------
#define P_STAGE_BYTES 20480
#define PGEMM_SMEM_BYTES 69632

__global__ __launch_bounds__(512, 2)
void pgemm_kernel(const float* __restrict__ gg,
                  const float* __restrict__ bb,
                  const float* __restrict__ mm,
                  const float* __restrict__ vv,
                  float* __restrict__ Out)
{
    extern __shared__ char sm[];
    const uint32_t sb = smem_u32(sm);
    float* sSh  = (float*)(sm + OFF_SH);
    float* S    = (float*)(sm + OFF_STAGE);

    const int tid = threadIdx.x;
    const int wid = tid >> 5;
    const int m0 = blockIdx.y * 128;
    const int n0 = blockIdx.x * 128;

    if (tid < 128) {
        int jj = n0 + tid;
        float inv = gg[jj] * rsqrtf(vv[jj] + EPSc);
        sSh[tid]  = bb[jj] - mm[jj] * inv;
    }
    __syncthreads();

    const int r = tid >> 2, k8 = (tid & 3) * 8;
    const int aoff = (m0 + r) * 512 + k8;
    const int woff = (n0 + r) * 512 + k8;
    const uint32_t so = (uint32_t)(r * TSTRIDE + k8) * 2;

    const int wm0 = (wid & 3) * 32;
    const int wn0 = (wid >> 2) * 32;

    wmma::fragment<wmma::accumulator, 16, 16, 16, float> acc[2][2];
#pragma unroll
    for (int i = 0; i < 2; i++)
#pragma unroll
        for (int j = 0; j < 2; j++) wmma::fill_fragment(acc[i][j], 0.0f);

    auto load_chunk = [&](int c, int stage) {
        const uint32_t base = sb + OFF_TILES + stage * P_STAGE_BYTES;
        const int k0 = c * 32;
        cp16(base + so,         g_af + aoff + k0);
        cp16(base + 10240 + so, g_pwf + woff + k0);
        CP_COMMIT();
    };

    load_chunk(0, 0);

#pragma unroll 1
    for (int c = 0; c < 16; c++) {
        CP_WAIT0();
        __syncthreads();
        if (c + 1 < 16) load_chunk(c + 1, (c + 1) & 1);

        char* st = sm + OFF_TILES + (c & 1) * P_STAGE_BYTES;
        __half* Afs = (__half*)(st);
        __half* Wfs = (__half*)(st + 10240);

#pragma unroll
        for (int kk = 0; kk < 32; kk += 16) {
#pragma unroll
            for (int j = 0; j < 2; j++) {
                wmma::fragment<wmma::matrix_b, 16, 16, 16, __half, wmma::col_major> bf;
                wmma::load_matrix_sync(bf, Wfs + (wn0 + j * 16) * TSTRIDE + kk, TSTRIDE);
#pragma unroll
                for (int i = 0; i < 2; i++) {
                    wmma::fragment<wmma::matrix_a, 16, 16, 16, __half, wmma::row_major> af;
                    wmma::load_matrix_sync(af, Afs + (wm0 + i * 16) * TSTRIDE + kk, TSTRIDE);
                    wmma::mma_sync(acc[i][j], af, bf, acc[i][j]);
                }
            }
        }
        __syncthreads();
    }

#pragma unroll
    for (int i = 0; i < 2; i++)
#pragma unroll
        for (int j = 0; j < 2; j++)
            wmma::store_matrix_sync(S + (wm0 + i * 16) * SSTRIDE + wn0 + j * 16,
                                    acc[i][j], SSTRIDE, wmma::mem_row_major);
    __syncthreads();

    for (int idx = tid; idx < 4096; idx += 512) {
        int mrow = idx >> 5, col = (idx & 31) * 4;
        float4 o;
        o.x = S[mrow * SSTRIDE + col + 0] + sSh[col + 0];
        o.y = S[mrow * SSTRIDE + col + 1] + sSh[col + 1];
        o.z = S[mrow * SSTRIDE + col + 2] + sSh[col + 2];
        o.w = S[mrow * SSTRIDE + col + 3] + sSh[col + 3];
        *reinterpret_cast<float4*>(Out + (size_t)(m0 + mrow) * 384 + n0 + col) = o;
    }
}

// ---------------------------------------------------------------------------
// Attention: one block per (b,h), 512 threads, single-fp16 q/k, 1-term scores.
// V is prefetched in phase 0 (Vh region doesn't overlap qf/kf; only Ph does)
// and waited with wait_group semantics so it streams under the scores phase.
// ---------------------------------------------------------------------------
#define AT_BIAS 0
#define AT_SC   832
#define AT_X    55104
#define AT_QF   (AT_X)
#define AT_KF   (AT_X + 5120)
#define AT_PH   (AT_X)
#define AT_VH   (AT_X + 27648)
#define ATTN_SMEM_BYTES 112704

__global__ __launch_bounds__(512, 2)
void attn_kernel(const float* __restrict__ attn_bias)
{
    extern __shared__ char smc[];
    const uint32_t sb = smem_u32(smc);
    float* bs = (float*)(smc + AT_BIAS);
    float* sc = (float*)(smc + AT_SC);                      // [64][212]
    __half* qf = (__half*)(smc + AT_QF);                    // [64][40]
    __half* kf = (__half*)(smc + AT_KF);                    // [208][40]
    __half* Ph = (__half*)(smc + AT_PH);                    // [64][216]
    __half* Vh = (__half*)(smc + AT_VH);                    // [208][72]

    const int blk = blockIdx.x;           // b*8 + h
    const int h = blk & 7;
    const int tid = threadIdx.x;
    const int wid = tid >> 5, lane = tid & 31;

    // phase 0: issue q/k loads (group A), then V loads (group B); zero pads; bias
    {
        const uint4* qg = (const uint4*)(g_qf + (size_t)blk * (Qq * KDc));
        for (int i = tid; i < 196; i += 512)
            cp16(sb + AT_QF + (i >> 2) * 80 + (i & 3) * 16, qg + i);
        const uint4* kg = (const uint4*)(g_kf + (size_t)blk * (Nn * KDc));
        for (int i = tid; i < 784; i += 512)
            cp16(sb + AT_KF + (i >> 2) * 80 + (i & 3) * 16, kg + i);
        CP_COMMIT();                                     // group A: q + k

        const uint4* vfg = (const uint4*)(g_vf + (size_t)blk * (Nn * VDc));
        for (int i = tid; i < 1568; i += 512)
            cp16(sb + AT_VH + (i >> 3) * 144 + (i & 7) * 16, vfg + i);
        CP_COMMIT();                                     // group B: V

        uint4 z = {0u, 0u, 0u, 0u};
        for (int i = tid; i < 75; i += 512) {            // q pad rows 49..63
            int row = 49 + i / 5, seg = i % 5;
            *(uint4*)(smc + AT_QF + row * 80 + seg * 16) = z;
        }
        for (int i = tid; i < 60; i += 512) {            // k pad rows 196..207
            int row = 196 + i / 5, seg = i % 5;
            *(uint4*)(smc + AT_KF + row * 80 + seg * 16) = z;
        }
        for (int i = tid; i < 108; i += 512) {           // V pad rows 196..207
            int row = 196 + i / 9, seg = i % 9;
            *(uint4*)(smc + AT_VH + row * 144 + seg * 16) = z;
        }
        for (int i = tid; i < 196; i += 512) bs[i] = attn_bias[h * Nn + i];
        CP_WAIT1();                                      // q/k done; V may be in flight
    }
    __syncthreads();

    // phase 1: scores = qf @ kf^T (1 term); 13 warps x 16-col strip
    if (wid < 13) {
        const int n0 = wid * 16;
        wmma::fragment<wmma::accumulator, 16, 16, 16, float> acc[4];
#pragma unroll
        for (int mt = 0; mt < 4; mt++) wmma::fill_fragment(acc[mt], 0.0f);
#pragma unroll
        for (int kk = 0; kk < 2; kk++) {
            wmma::fragment<wmma::matrix_b, 16, 16, 16, __half, wmma::col_major> bf;
            wmma::load_matrix_sync(bf, kf + n0 * 40 + kk * 16, 40);
#pragma unroll
            for (int mt = 0; mt < 4; mt++) {
                wmma::fragment<wmma::matrix_a, 16, 16, 16, __half, wmma::row_major> af;
                wmma::load_matrix_sync(af, qf + mt * 16 * 40 + kk * 16, 40);
                wmma::mma_sync(acc[mt], af, bf, acc[mt]);
            }
        }
#pragma unroll
        for (int mt = 0; mt < 4; mt++)
            wmma::store_matrix_sync(sc + mt * 16 * 212 + n0, acc[mt], 212, wmma::mem_row_major);
    }
    __syncthreads();   // qf/kf dead; Ph region writable

    // phase 2: zero Ph pad rows (overlays dead qf/kf)
    {
        uint4 z = {0u, 0u, 0u, 0u};
        for (int i = tid; i < 405; i += 512) {
            int row = 49 + i / 27, seg = i % 27;
            *(uint4*)(smc + AT_PH + row * 432 + seg * 16) = z;
        }
    }

    // phase 3: softmax (fp32) -> Ph fp16 (SCALEc folded into q)
    for (int row = wid; row < Qq; row += 16) {
        int qi2 = 2 * (row / 7), qj2 = 2 * (row % 7);
        float mx = -1e30f;
        for (int n = lane; n < Nn; n += 32) {
            int ki = n / 14, kj = n - ki * 14;
            float val = sc[row * 212 + n] + bs[abs(qi2 - ki) * 14 + abs(qj2 - kj)];
            sc[row * 212 + n] = val;
            mx = fmaxf(mx, val);
        }
#pragma unroll
        for (int o = 16; o > 0; o >>= 1)
            mx = fmaxf(mx, __shfl_xor_sync(0xffffffffu, mx, o));
        float sum = 0.0f;
        for (int n = lane; n < Nn; n += 32) {
            float e = __expf(sc[row * 212 + n] - mx);
            sc[row * 212 + n] = e;
            sum += e;
        }
#pragma unroll
        for (int o = 16; o > 0; o >>= 1)
            sum += __shfl_xor_sync(0xffffffffu, sum, o);
        float rinv = 1.0f / sum;
        for (int n = lane; n < 208; n += 32) {
            float p = (n < Nn) ? sc[row * 212 + n] * rinv : 0.0f;
            Ph[row * 216 + n] = __float2half_rn(p);
        }
    }
    CP_WAIT0();        // V resident
    __syncthreads();

    // phase 4: AV = Ph @ Vh; 16 warps, one 16x16 tile each
    {
        const int mi = wid >> 2, ni = wid & 3;
        wmma::fragment<wmma::accumulator, 16, 16, 16, float> acc;
        wmma::fill_fragment(acc, 0.0f);
#pragma unroll
        for (int kk = 0; kk < 13; kk++) {
            wmma::fragment<wmma::matrix_a, 16, 16, 16, __half, wmma::row_major> pf;
            wmma::fragment<wmma::matrix_b, 16, 16, 16, __half, wmma::row_major> vf;
            wmma::load_matrix_sync(pf, Ph + mi * 16 * 216 + kk * 16, 216);
            wmma::load_matrix_sync(vf, Vh + kk * 16 * 72 + ni * 16, 72);
            wmma::mma_sync(acc, pf, vf, acc);
        }
        wmma::store_matrix_sync(sc + mi * 16 * 68 + ni * 16, acc, 68, wmma::mem_row_major);
    }
    __syncthreads();

    // phase 5: hardswish + fp16 store to g_af
    {
        const int b = blk >> 3;
        for (int i = tid; i < 1568; i += 512) {
            int qr = i >> 5, vd = (i & 31) * 2;
            float t0 = sc[qr * 68 + vd];
            float t1 = sc[qr * 68 + vd + 1];
            float o0 = t0 * fminf(fmaxf(t0 + 3.0f, 0.0f), 6.0f) * (1.0f / 6.0f);
            float o1 = t1 * fminf(fmaxf(t1 + 3.0f, 0.0f), 6.0f) * (1.0f / 6.0f);
            size_t off = ((size_t)(b * Qq + qr)) * 512 + h * VDc + vd;
            *reinterpret_cast<__half2*>(g_af + off) = __floats2half2_rn(o0, o1);
        }
    }
}

// ---------------------------------------------------------------------------
extern "C" void kernel_launch(void* const* d_in, const int* in_sizes, int n_in,
                              void* d_out, int out_size)
{
    const float* x      = (const float*)d_in[0];
    const float* kv_w   = (const float*)d_in[1];
    const float* kv_g   = (const float*)d_in[2];
    const float* kv_b   = (const float*)d_in[3];
    const float* kv_m   = (const float*)d_in[4];
    const float* kv_v   = (const float*)d_in[5];
    const float* q_w    = (const float*)d_in[6];
    const float* q_g    = (const float*)d_in[7];
    const float* q_b    = (const float*)d_in[8];
    const float* q_m    = (const float*)d_in[9];
    const float* q_v    = (const float*)d_in[10];
    const float* proj_w = (const float*)d_in[11];
    const float* proj_g = (const float*)d_in[12];
    const float* proj_b = (const float*)d_in[13];
    const float* proj_m = (const float*)d_in[14];
    const float* proj_v = (const float*)d_in[15];
    const float* attn_bias = (const float*)d_in[16];
    float* out = (float*)d_out;

    split_all_kernel<<<(NX + NW1 + NW2 + NW3 + 255) / 256, 256>>>(
        x, kv_w, q_w, proj_w, proj_g, proj_v);

    cudaFuncSetAttribute(kvq_gemm_kernel, cudaFuncAttributeMaxDynamicSharedMemorySize, GEMM_SMEM_BYTES);
    cudaFuncSetAttribute(pgemm_kernel, cudaFuncAttributeMaxDynamicSharedMemorySize, PGEMM_SMEM_BYTES);
    cudaFuncSetAttribute(attn_kernel, cudaFuncAttributeMaxDynamicSharedMemorySize, ATTN_SMEM_BYTES);

    kvq_gemm_kernel<<<TOTAL_B, 512, GEMM_SMEM_BYTES>>>(
        kv_g, kv_b, kv_m, kv_v, q_g, q_b, q_m, q_v);

    attn_kernel<<<Bc * Hh, 512, ATTN_SMEM_BYTES>>>(attn_bias);

    pgemm_kernel<<<dim3(3, 98), 512, PGEMM_SMEM_BYTES>>>(proj_g, proj_b, proj_m, proj_v, out);
}

// round 16
// speedup vs baseline: 1.7542x; 1.1709x over previous
#include <cuda_runtime.h>
#include <cuda_bf16.h>
#include <cuda_fp16.h>
#include <mma.h>
#include <cstdint>

using namespace nvcuda;

// ---------------- problem constants ----------------
#define Bc   256
#define Nn   196
#define Hh   8
#define KDc  32
#define VDc  64
#define Qq   49
#define EPSc 1e-5f
#define SCALEc 0.17677669529663689f  // 32^-0.5

// ---------------- device scratch (all fp16) ----------------
__device__ __half g_xh[Bc*Nn*256];                     // x fp16
__device__ __half g_kwf[256*256];                      // kv_w K-part, reordered
__device__ __half g_vwf[512*256];                      // kv_w V-part, reordered
__device__ __half g_qwf[256*256];                      // q_w
__device__ __half g_pwf[384*512];                      // proj W (inv-scaled)
__device__ __half g_af[Bc*Qq*512];                     // attn out
__device__ __half g_kf[Bc*Hh*Nn*KDc];                  // [bh,n,d]
__device__ __half g_vf[Bc*Hh*Nn*VDc];                  // [bh,n,d]
__device__ __half g_qf[Bc*Hh*Qq*KDc];                  // [bh,q,d] (SCALEc folded)

// ---------------- cp.async helpers ----------------
__device__ __forceinline__ void cp16(uint32_t dst, const void* src) {
    asm volatile("cp.async.cg.shared.global [%0], [%1], 16;" :: "r"(dst), "l"(src));
}
#define CP_COMMIT() asm volatile("cp.async.commit_group;" ::: "memory")
#define CP_WAIT0()  asm volatile("cp.async.wait_group 0;" ::: "memory")

__device__ __forceinline__ uint32_t smem_u32(const void* p) {
    uint32_t a;
    asm("{ .reg .u64 t; cvta.to.shared.u64 t, %1; cvt.u32.u64 %0, t; }" : "=r"(a) : "l"(p));
    return a;
}

// ---------------- fused precompute ----------------
#define NX  (Bc*Nn*256/4)
#define NW1 (768*256/4)
#define NW2 (256*256/4)
#define NW3 (384*512/4)
__global__ void split_all_kernel(const float* __restrict__ x,
                                 const float* __restrict__ kv_w,
                                 const float* __restrict__ q_w,
                                 const float* __restrict__ proj_w,
                                 const float* __restrict__ proj_g,
                                 const float* __restrict__ proj_v)
{
    int i = blockIdx.x * blockDim.x + threadIdx.x;
    if (i < NX) {
        float4 t = reinterpret_cast<const float4*>(x)[i];
        reinterpret_cast<__half2*>(g_xh)[i*2]   = __floats2half2_rn(t.x, t.y);
        reinterpret_cast<__half2*>(g_xh)[i*2+1] = __floats2half2_rn(t.z, t.w);
    } else if (i < NX + NW1) {
        int j = i - NX;
        int r = j >> 6, c4 = j & 63;
        float4 t = reinterpret_cast<const float4*>(kv_w)[j];
        int h = r / 96, c = r - h * 96;
        int di;
        __half* dst;
        if (c < KDc) { di = (h * 32 + c) * 64 + c4;          dst = g_kwf; }
        else         { di = (h * 64 + (c - KDc)) * 64 + c4;  dst = g_vwf; }
        reinterpret_cast<__half2*>(dst)[di*2]   = __floats2half2_rn(t.x, t.y);
        reinterpret_cast<__half2*>(dst)[di*2+1] = __floats2half2_rn(t.z, t.w);
    } else if (i < NX + NW1 + NW2) {
        int j = i - NX - NW1;
        float4 t = reinterpret_cast<const float4*>(q_w)[j];
        reinterpret_cast<__half2*>(g_qwf)[j*2]   = __floats2half2_rn(t.x, t.y);
        reinterpret_cast<__half2*>(g_qwf)[j*2+1] = __floats2half2_rn(t.z, t.w);
    } else if (i < NX + NW1 + NW2 + NW3) {
        int j = i - NX - NW1 - NW2;
        int row = j >> 7;
        float inv = proj_g[row] * rsqrtf(proj_v[row] + EPSc);
        float4 t = reinterpret_cast<const float4*>(proj_w)[j];
        t.x *= inv; t.y *= inv; t.z *= inv; t.w *= inv;
        reinterpret_cast<__half2*>(g_pwf)[j*2]   = __floats2half2_rn(t.x, t.y);
        reinterpret_cast<__half2*>(g_pwf)[j*2+1] = __floats2half2_rn(t.z, t.w);
    }
}

// ---------------- GEMM smem layout ----------------
#define TSTRIDE 40
#define OFF_ROW   64
#define OFF_INV   576
#define OFF_SH    1088
#define OFF_TILES 2048
#define STAGE_BYTES 20480      // Ah | Wf
#define OFF_STAGE 2048
#define SSTRIDE   132
#define GEMM_SMEM_BYTES 69632

#define KB 784
#define VB 2352
#define TOTAL_B 2548

// ---------------------------------------------------------------------------
// Fused K/V/q GEMM, uniform single-term fp16, 512 threads, 32x32 warp tiles.
// ---------------------------------------------------------------------------
__global__ __launch_bounds__(512, 2)
void kvq_gemm_kernel(const float* __restrict__ kv_g, const float* __restrict__ kv_b,
                     const float* __restrict__ kv_m, const float* __restrict__ kv_v,
                     const float* __restrict__ q_g,  const float* __restrict__ q_b,
                     const float* __restrict__ q_m,  const float* __restrict__ q_v)
{
    extern __shared__ char sm[];
    const uint32_t sb = smem_u32(sm);
    int*   rowoff = (int*)(sm + OFF_ROW);
    float* sInv   = (float*)(sm + OFF_INV);
    float* sSh    = (float*)(sm + OFF_SH);
    float* S      = (float*)(sm + OFF_STAGE);

    const int bx = blockIdx.x;
    int mode, n0, m0;
    if (bx < KB)      { mode = 0; n0 = (bx & 1) * 128;  m0 = (bx >> 1) * 128; }
    else if (bx < VB) { int i = bx - KB; mode = 1; n0 = (i & 3) * 128; m0 = (i >> 2) * 128; }
    else              { int i = bx - VB; mode = 2; n0 = (i & 1) * 128; m0 = (i >> 1) * 128; }

    const __half* Wf = (mode == 0) ? g_kwf : (mode == 1) ? g_vwf : g_qwf;

    const int tid = threadIdx.x;
    const int wid = tid >> 5;

    if (tid < 128) {
        int m = m0 + tid;
        int off;
        if (mode == 2) {
            int b = m / Qq, qq = m % Qq;
            int n = (qq / 7) * 28 + (qq % 7) * 2;
            off = (b * Nn + n) * 256;
        } else {
            off = m * 256;
        }
        rowoff[tid] = off;
        int jj = n0 + tid;
        int jo;
        const float *gg, *bb, *mm, *vv;
        if (mode == 0)      { jo = (jj >> 5) * 96 + (jj & 31);        gg = kv_g; bb = kv_b; mm = kv_m; vv = kv_v; }
        else if (mode == 1) { jo = (jj >> 6) * 96 + KDc + (jj & 63);  gg = kv_g; bb = kv_b; mm = kv_m; vv = kv_v; }
        else                { jo = jj;                                 gg = q_g;  bb = q_b;  mm = q_m;  vv = q_v;  }
        float inv = gg[jo] * rsqrtf(vv[jo] + EPSc);
        float sh  = bb[jo] - mm[jo] * inv;
        if (mode == 2) { inv *= SCALEc; sh *= SCALEc; }
        sInv[tid] = inv;
        sSh[tid]  = sh;
    }
    __syncthreads();

    const int r = tid >> 2, k8 = (tid & 3) * 8;
    const int aoff = rowoff[r] + k8;
    const int woff = (n0 + r) * 256 + k8;
    const uint32_t so = (uint32_t)(r * TSTRIDE + k8) * 2;

    const int wm0 = (wid & 3) * 32;
    const int wn0 = (wid >> 2) * 32;

    wmma::fragment<wmma::accumulator, 16, 16, 16, float> acc[2][2];
#pragma unroll
    for (int i = 0; i < 2; i++)
#pragma unroll
        for (int j = 0; j < 2; j++) wmma::fill_fragment(acc[i][j], 0.0f);

    auto load1 = [&](int c, int stage) {
        const uint32_t base = sb + OFF_TILES + stage * STAGE_BYTES;
        const int k0 = c * 32;
        cp16(base + so,         g_xh + aoff + k0);
        cp16(base + 10240 + so, Wf + woff + k0);
        CP_COMMIT();
    };
    load1(0, 0);

#pragma unroll 1
    for (int c = 0; c < 8; c++) {
        CP_WAIT0();
        __syncthreads();
        if (c + 1 < 8) load1(c + 1, (c + 1) & 1);
        char* st = sm + OFF_TILES + (c & 1) * STAGE_BYTES;
        __half* Ahs = (__half*)(st);
        __half* Wfs = (__half*)(st + 10240);
#pragma unroll
        for (int kk = 0; kk < 32; kk += 16) {
#pragma unroll
            for (int j = 0; j < 2; j++) {
                wmma::fragment<wmma::matrix_b, 16, 16, 16, __half, wmma::col_major> bf;
                wmma::load_matrix_sync(bf, Wfs + (wn0 + j * 16) * TSTRIDE + kk, TSTRIDE);
#pragma unroll
                for (int i = 0; i < 2; i++) {
                    wmma::fragment<wmma::matrix_a, 16, 16, 16, __half, wmma::row_major> af;
                    wmma::load_matrix_sync(af, Ahs + (wm0 + i * 16) * TSTRIDE + kk, TSTRIDE);
                    wmma::mma_sync(acc[i][j], af, bf, acc[i][j]);
                }
            }
        }
        __syncthreads();
    }

#pragma unroll
    for (int i = 0; i < 2; i++)
#pragma unroll
        for (int j = 0; j < 2; j++)
            wmma::store_matrix_sync(S + (wm0 + i * 16) * SSTRIDE + wn0 + j * 16,
                                    acc[i][j], SSTRIDE, wmma::mem_row_major);
    __syncthreads();

    for (int idx = tid; idx < 8192; idx += 512) {
        int mrow = idx >> 6, pair = idx & 63, col = pair * 2;
        int jj = n0 + col;
        int m = m0 + mrow;
        float v0 = S[mrow * SSTRIDE + col]     * sInv[col]     + sSh[col];
        float v1 = S[mrow * SSTRIDE + col + 1] * sInv[col + 1] + sSh[col + 1];
        __half2 hv = __floats2half2_rn(v0, v1);
        if (mode == 0) {
            int h = jj >> 5, d = jj & 31;
            int b = m / Nn, n = m - b * Nn;
            *reinterpret_cast<__half2*>(g_kf + ((size_t)((b * Hh + h) * Nn + n)) * KDc + d) = hv;
        } else if (mode == 1) {
            int h = jj >> 6, d = jj & 63;
            int b = m / Nn, n = m - b * Nn;
            *reinterpret_cast<__half2*>(g_vf + ((size_t)((b * Hh + h) * Nn + n)) * VDc + d) = hv;
        } else {
            int h = jj >> 5, d = jj & 31;
            int b = m / Qq, qq = m - b * Qq;
            *reinterpret_cast<__half2*>(g_qf + ((size_t)((b * Hh + h) * Qq + qq)) * KDc + d) = hv;
        }
    }
}

// ---------------------------------------------------------------------------
// proj GEMM: single-term fp16, 512 threads, 32x32 warp tiles.
// ---------------------------------------------------------------------------
#define P_STAGE_BYTES 20480
#define PGEMM_SMEM_BYTES 69632

__global__ __launch_bounds__(512, 2)
void pgemm_kernel(const float* __restrict__ gg,
                  const float* __restrict__ bb,
                  const float* __restrict__ mm,
                  const float* __restrict__ vv,
                  float* __restrict__ Out)
{
    extern __shared__ char sm[];
    const uint32_t sb = smem_u32(sm);
    float* sSh  = (float*)(sm + OFF_SH);
    float* S    = (float*)(sm + OFF_STAGE);

    const int tid = threadIdx.x;
    const int wid = tid >> 5;
    const int m0 = blockIdx.y * 128;
    const int n0 = blockIdx.x * 128;

    if (tid < 128) {
        int jj = n0 + tid;
        float inv = gg[jj] * rsqrtf(vv[jj] + EPSc);
        sSh[tid]  = bb[jj] - mm[jj] * inv;
    }
    __syncthreads();

    const int r = tid >> 2, k8 = (tid & 3) * 8;
    const int aoff = (m0 + r) * 512 + k8;
    const int woff = (n0 + r) * 512 + k8;
    const uint32_t so = (uint32_t)(r * TSTRIDE + k8) * 2;

    const int wm0 = (wid & 3) * 32;
    const int wn0 = (wid >> 2) * 32;

    wmma::fragment<wmma::accumulator, 16, 16, 16, float> acc[2][2];
#pragma unroll
    for (int i = 0; i < 2; i++)
#pragma unroll
        for (int j = 0; j < 2; j++) wmma::fill_fragment(acc[i][j], 0.0f);

    auto load_chunk = [&](int c, int stage) {
        const uint32_t base = sb + OFF_TILES + stage * P_STAGE_BYTES;
        const int k0 = c * 32;
        cp16(base + so,         g_af + aoff + k0);
        cp16(base + 10240 + so, g_pwf + woff + k0);
        CP_COMMIT();
    };

    load_chunk(0, 0);

#pragma unroll 1
    for (int c = 0; c < 16; c++) {
        CP_WAIT0();
        __syncthreads();
        if (c + 1 < 16) load_chunk(c + 1, (c + 1) & 1);

        char* st = sm + OFF_TILES + (c & 1) * P_STAGE_BYTES;
        __half* Afs = (__half*)(st);
        __half* Wfs = (__half*)(st + 10240);

#pragma unroll
        for (int kk = 0; kk < 32; kk += 16) {
#pragma unroll
            for (int j = 0; j < 2; j++) {
                wmma::fragment<wmma::matrix_b, 16, 16, 16, __half, wmma::col_major> bf;
                wmma::load_matrix_sync(bf, Wfs + (wn0 + j * 16) * TSTRIDE + kk, TSTRIDE);
#pragma unroll
                for (int i = 0; i < 2; i++) {
                    wmma::fragment<wmma::matrix_a, 16, 16, 16, __half, wmma::row_major> af;
                    wmma::load_matrix_sync(af, Afs + (wm0 + i * 16) * TSTRIDE + kk, TSTRIDE);
                    wmma::mma_sync(acc[i][j], af, bf, acc[i][j]);
                }
            }
        }
        __syncthreads();
    }

#pragma unroll
    for (int i = 0; i < 2; i++)
#pragma unroll
        for (int j = 0; j < 2; j++)
            wmma::store_matrix_sync(S + (wm0 + i * 16) * SSTRIDE + wn0 + j * 16,
                                    acc[i][j], SSTRIDE, wmma::mem_row_major);
    __syncthreads();

    for (int idx = tid; idx < 4096; idx += 512) {
        int mrow = idx >> 5, col = (idx & 31) * 4;
        float4 o;
        o.x = S[mrow * SSTRIDE + col + 0] + sSh[col + 0];
        o.y = S[mrow * SSTRIDE + col + 1] + sSh[col + 1];
        o.z = S[mrow * SSTRIDE + col + 2] + sSh[col + 2];
        o.w = S[mrow * SSTRIDE + col + 3] + sSh[col + 3];
        *reinterpret_cast<float4*>(Out + (size_t)(m0 + mrow) * 384 + n0 + col) = o;
    }
}

// ---------------------------------------------------------------------------
// Attention: one block per (b,h), 512 threads, 75.8 KB smem.
// scores accumulate fp16 directly into scP (which doubles as P);
// in-register softmax; V prefetched into dead qf/kf overlay under softmax.
// layout (bytes): bias[832) | scP fp16 [64][216] | X{qf[64][40]+kf[208][40] | Vh[208][72]} | Ot fp32 [64][68]
// ---------------------------------------------------------------------------
#define AT_BIAS 0
#define AT_SCP  832
#define AT_QF   28480
#define AT_KF   33600
#define AT_VH   28480
#define AT_OUT  58432
#define ATTN_SMEM_BYTES 75840

__global__ __launch_bounds__(512, 2)
void attn_kernel(const float* __restrict__ attn_bias)
{
    extern __shared__ char smc[];
    const uint32_t sb = smem_u32(smc);
    float* bs  = (float*)(smc + AT_BIAS);
    __half* scP = (__half*)(smc + AT_SCP);   // [64][216]; becomes P after softmax
    __half* qf  = (__half*)(smc + AT_QF);    // [64][40]
    __half* kf  = (__half*)(smc + AT_KF);    // [208][40]
    __half* Vh  = (__half*)(smc + AT_VH);    // [208][72]
    float*  Ot  = (float*)(smc + AT_OUT);    // [64][68]

    const int blk = blockIdx.x;           // b*8 + h
    const int h = blk & 7;
    const int tid = threadIdx.x;
    const int wid = tid >> 5, lane = tid & 31;

    // phase 0: load q, k (fp16); bias
    {
        const uint4* qg = (const uint4*)(g_qf + (size_t)blk * (Qq * KDc));
        for (int i = tid; i < 196; i += 512)
            cp16(sb + AT_QF + (i >> 2) * 80 + (i & 3) * 16, qg + i);
        const uint4* kg = (const uint4*)(g_kf + (size_t)blk * (Nn * KDc));
        for (int i = tid; i < 784; i += 512)
            cp16(sb + AT_KF + (i >> 2) * 80 + (i & 3) * 16, kg + i);
        CP_COMMIT();
        // zero q pad rows (49..63): keeps score rows finite/deterministic cheaply
        uint4 z = {0u, 0u, 0u, 0u};
        for (int i = tid; i < 75; i += 512) {
            int row = 49 + i / 5, seg = i % 5;
            *(uint4*)(smc + AT_QF + row * 80 + seg * 16) = z;
        }
        for (int i = tid; i < 196; i += 512) bs[i] = attn_bias[h * Nn + i];
        CP_WAIT0();
    }
    __syncthreads();

    // phase 1: scores = qf @ kf^T, fp16 accumulators -> scP (stride 216)
    if (wid < 13) {
        const int n0 = wid * 16;
        wmma::fragment<wmma::accumulator, 16, 16, 16, __half> acc[4];
#pragma unroll
        for (int mt = 0; mt < 4; mt++) wmma::fill_fragment(acc[mt], __float2half(0.0f));
#pragma unroll
        for (int kk = 0; kk < 2; kk++) {
            wmma::fragment<wmma::matrix_b, 16, 16, 16, __half, wmma::col_major> bf;
            wmma::load_matrix_sync(bf, kf + n0 * 40 + kk * 16, 40);
#pragma unroll
            for (int mt = 0; mt < 4; mt++) {
                wmma::fragment<wmma::matrix_a, 16, 16, 16, __half, wmma::row_major> af;
                wmma::load_matrix_sync(af, qf + mt * 16 * 40 + kk * 16, 40);
                wmma::mma_sync(acc[mt], af, bf, acc[mt]);
            }
        }
#pragma unroll
        for (int mt = 0; mt < 4; mt++)
            wmma::store_matrix_sync(scP + mt * 16 * 216 + n0, acc[mt], 216, wmma::mem_row_major);
    }
    __syncthreads();   // qf/kf dead

    // phase 2: prefetch V into X overlay; zero V pad rows (NaN x 0 hazard in AV)
    {
        const uint4* vfg = (const uint4*)(g_vf + (size_t)blk * (Nn * VDc));
        for (int i = tid; i < 1568; i += 512)
            cp16(sb + AT_VH + (i >> 3) * 144 + (i & 7) * 16, vfg + i);
        CP_COMMIT();
        uint4 z = {0u, 0u, 0u, 0u};
        for (int i = tid; i < 108; i += 512) {
            int row = 196 + i / 9, seg = i % 9;
            *(uint4*)(smc + AT_VH + row * 144 + seg * 16) = z;
        }
    }

    // phase 3: in-register softmax on scP rows (SCALEc folded into q)
    for (int row = wid; row < Qq; row += 16) {
        int qi2 = 2 * (row / 7), qj2 = 2 * (row % 7);
        float v[7];
        float mx = -1e30f;
#pragma unroll
        for (int t = 0; t < 7; t++) {
            int n = lane + t * 32;
            if (n < Nn) {
                int ki = n / 14, kj = n - ki * 14;
                float val = __half2float(scP[row * 216 + n]) + bs[abs(qi2 - ki) * 14 + abs(qj2 - kj)];
                v[t] = val;
                mx = fmaxf(mx, val);
            }
        }
#pragma unroll
        for (int o = 16; o > 0; o >>= 1)
            mx = fmaxf(mx, __shfl_xor_sync(0xffffffffu, mx, o));
        float sum = 0.0f;
#pragma unroll
        for (int t = 0; t < 7; t++) {
            int n = lane + t * 32;
            if (n < Nn) {
                float e = __expf(v[t] - mx);
                v[t] = e;
                sum += e;
            }
        }
#pragma unroll
        for (int o = 16; o > 0; o >>= 1)
            sum += __shfl_xor_sync(0xffffffffu, sum, o);
        float rinv = 1.0f / sum;
#pragma unroll
        for (int t = 0; t < 7; t++) {
            int n = lane + t * 32;
            if (n < Nn)        scP[row * 216 + n] = __float2half_rn(v[t] * rinv);
            else if (n < 208)  scP[row * 216 + n] = __float2half_rn(0.0f);
        }
    }
    CP_WAIT0();        // V resident
    __syncthreads();

    // phase 4: AV = P @ Vh; 16 warps, one 16x16 tile each -> Ot fp32
    {
        const int mi = wid >> 2, ni = wid & 3;
        wmma::fragment<wmma::accumulator, 16, 16, 16, float> acc;
        wmma::fill_fragment(acc, 0.0f);
#pragma unroll
        for (int kk = 0; kk < 13; kk++) {
            wmma::fragment<wmma::matrix_a, 16, 16, 16, __half, wmma::row_major> pf;
            wmma::fragment<wmma::matrix_b, 16, 16, 16, __half, wmma::row_major> vf;
            wmma::load_matrix_sync(pf, scP + mi * 16 * 216 + kk * 16, 216);
            wmma::load_matrix_sync(vf, Vh + kk * 16 * 72 + ni * 16, 72);
            wmma::mma_sync(acc, pf, vf, acc);
        }
        wmma::store_matrix_sync(Ot + mi * 16 * 68 + ni * 16, acc, 68, wmma::mem_row_major);
    }
    __syncthreads();

    // phase 5: hardswish + fp16 store to g_af
    {
        const int b = blk >> 3;
        for (int i = tid; i < 1568; i += 512) {
            int qr = i >> 5, vd = (i & 31) * 2;
            float t0 = Ot[qr * 68 + vd];
            float t1 = Ot[qr * 68 + vd + 1];
            float o0 = t0 * fminf(fmaxf(t0 + 3.0f, 0.0f), 6.0f) * (1.0f / 6.0f);
            float o1 = t1 * fminf(fmaxf(t1 + 3.0f, 0.0f), 6.0f) * (1.0f / 6.0f);
            size_t off = ((size_t)(b * Qq + qr)) * 512 + h * VDc + vd;
            *reinterpret_cast<__half2*>(g_af + off) = __floats2half2_rn(o0, o1);
        }
    }
}

// ---------------------------------------------------------------------------
extern "C" void kernel_launch(void* const* d_in, const int* in_sizes, int n_in,
                              void* d_out, int out_size)
{
    const float* x      = (const float*)d_in[0];
    const float* kv_w   = (const float*)d_in[1];
    const float* kv_g   = (const float*)d_in[2];
    const float* kv_b   = (const float*)d_in[3];
    const float* kv_m   = (const float*)d_in[4];
    const float* kv_v   = (const float*)d_in[5];
    const float* q_w    = (const float*)d_in[6];
    const float* q_g    = (const float*)d_in[7];
    const float* q_b    = (const float*)d_in[8];
    const float* q_m    = (const float*)d_in[9];
    const float* q_v    = (const float*)d_in[10];
    const float* proj_w = (const float*)d_in[11];
    const float* proj_g = (const float*)d_in[12];
    const float* proj_b = (const float*)d_in[13];
    const float* proj_m = (const float*)d_in[14];
    const float* proj_v = (const float*)d_in[15];
    const float* attn_bias = (const float*)d_in[16];
    float* out = (float*)d_out;

    split_all_kernel<<<(NX + NW1 + NW2 + NW3 + 255) / 256, 256>>>(
        x, kv_w, q_w, proj_w, proj_g, proj_v);

    cudaFuncSetAttribute(kvq_gemm_kernel, cudaFuncAttributeMaxDynamicSharedMemorySize, GEMM_SMEM_BYTES);
    cudaFuncSetAttribute(pgemm_kernel, cudaFuncAttributeMaxDynamicSharedMemorySize, PGEMM_SMEM_BYTES);
    cudaFuncSetAttribute(attn_kernel, cudaFuncAttributeMaxDynamicSharedMemorySize, ATTN_SMEM_BYTES);

    kvq_gemm_kernel<<<TOTAL_B, 512, GEMM_SMEM_BYTES>>>(
        kv_g, kv_b, kv_m, kv_v, q_g, q_b, q_m, q_v);

    attn_kernel<<<Bc * Hh, 512, ATTN_SMEM_BYTES>>>(attn_bias);

    pgemm_kernel<<<dim3(3, 98), 512, PGEMM_SMEM_BYTES>>>(proj_g, proj_b, proj_m, proj_v, out);
}

// round 17
// speedup vs baseline: 1.8674x; 1.0645x over previous
#include <cuda_runtime.h>
#include <cuda_bf16.h>
#include <cuda_fp16.h>
#include <mma.h>
#include <cstdint>

using namespace nvcuda;

// ---------------- problem constants ----------------
#define Bc   256
#define Nn   196
#define Hh   8
#define KDc  32
#define VDc  64
#define Qq   49
#define EPSc 1e-5f
#define SCALEc 0.17677669529663689f  // 32^-0.5

// ---------------- device scratch (all fp16) ----------------
__device__ __half g_xh[Bc*Nn*256];                     // x fp16
__device__ __half g_kwf[256*256];                      // kv_w K-part, reordered
__device__ __half g_vwf[512*256];                      // kv_w V-part, reordered
__device__ __half g_qwf[256*256];                      // q_w
__device__ __half g_pwf[384*512];                      // proj W (inv-scaled)
__device__ __half g_af[Bc*Qq*512];                     // attn out
__device__ __half g_kf[Bc*Hh*Nn*KDc];                  // [bh,n,d]
__device__ __half g_vf[Bc*Hh*Nn*VDc];                  // [bh,n,d]
__device__ __half g_qf[Bc*Hh*Qq*KDc];                  // [bh,q,d] (SCALEc folded)

// ---------------- cp.async helpers ----------------
__device__ __forceinline__ void cp16(uint32_t dst, const void* src) {
    asm volatile("cp.async.cg.shared.global [%0], [%1], 16;" :: "r"(dst), "l"(src));
}
#define CP_COMMIT() asm volatile("cp.async.commit_group;" ::: "memory")
#define CP_WAIT0()  asm volatile("cp.async.wait_group 0;" ::: "memory")

__device__ __forceinline__ uint32_t smem_u32(const void* p) {
    uint32_t a;
    asm("{ .reg .u64 t; cvta.to.shared.u64 t, %1; cvt.u32.u64 %0, t; }" : "=r"(a) : "l"(p));
    return a;
}

// ---------------- fused precompute ----------------
#define NX  (Bc*Nn*256/4)
#define NW1 (768*256/4)
#define NW2 (256*256/4)
#define NW3 (384*512/4)
__global__ void split_all_kernel(const float* __restrict__ x,
                                 const float* __restrict__ kv_w,
                                 const float* __restrict__ q_w,
                                 const float* __restrict__ proj_w,
                                 const float* __restrict__ proj_g,
                                 const float* __restrict__ proj_v)
{
    int i = blockIdx.x * blockDim.x + threadIdx.x;
    if (i < NX) {
        float4 t = reinterpret_cast<const float4*>(x)[i];
        reinterpret_cast<__half2*>(g_xh)[i*2]   = __floats2half2_rn(t.x, t.y);
        reinterpret_cast<__half2*>(g_xh)[i*2+1] = __floats2half2_rn(t.z, t.w);
    } else if (i < NX + NW1) {
        int j = i - NX;
        int r = j >> 6, c4 = j & 63;
        float4 t = reinterpret_cast<const float4*>(kv_w)[j];
        int h = r / 96, c = r - h * 96;
        int di;
        __half* dst;
        if (c < KDc) { di = (h * 32 + c) * 64 + c4;          dst = g_kwf; }
        else         { di = (h * 64 + (c - KDc)) * 64 + c4;  dst = g_vwf; }
        reinterpret_cast<__half2*>(dst)[di*2]   = __floats2half2_rn(t.x, t.y);
        reinterpret_cast<__half2*>(dst)[di*2+1] = __floats2half2_rn(t.z, t.w);
    } else if (i < NX + NW1 + NW2) {
        int j = i - NX - NW1;
        float4 t = reinterpret_cast<const float4*>(q_w)[j];
        reinterpret_cast<__half2*>(g_qwf)[j*2]   = __floats2half2_rn(t.x, t.y);
        reinterpret_cast<__half2*>(g_qwf)[j*2+1] = __floats2half2_rn(t.z, t.w);
    } else if (i < NX + NW1 + NW2 + NW3) {
        int j = i - NX - NW1 - NW2;
        int row = j >> 7;
        float inv = proj_g[row] * rsqrtf(proj_v[row] + EPSc);
        float4 t = reinterpret_cast<const float4*>(proj_w)[j];
        t.x *= inv; t.y *= inv; t.z *= inv; t.w *= inv;
        reinterpret_cast<__half2*>(g_pwf)[j*2]   = __floats2half2_rn(t.x, t.y);
        reinterpret_cast<__half2*>(g_pwf)[j*2+1] = __floats2half2_rn(t.z, t.w);
    }
}

// ---------------- GEMM smem layout (K-chunk = 64) ----------------
#define TSTRIDE 72                 // 64 + 8 pad, fp16 elements
#define OFF_ROW   64
#define OFF_INV   576
#define OFF_SH    1088
#define OFF_TILES 2048
#define TILE_BYTES 18432           // 128 x 72 fp16
#define STAGE_BYTES 36864          // A | W
#define OFF_STAGE 2048
#define SSTRIDE   132
#define GEMM_SMEM_BYTES (2048 + 2*STAGE_BYTES)   // 75776

#define KB 784
#define VB 2352
#define TOTAL_B 2548

// ---------------------------------------------------------------------------
// Fused K/V/q GEMM, single-term fp16, 512 threads, 32x32 warp tiles,
// K-chunk 64, one barrier per chunk (bottom barrier proven redundant).
// ---------------------------------------------------------------------------
__global__ __launch_bounds__(512, 2)
void kvq_gemm_kernel(const float* __restrict__ kv_g, const float* __restrict__ kv_b,
                     const float* __restrict__ kv_m, const float* __restrict__ kv_v,
                     const float* __restrict__ q_g,  const float* __restrict__ q_b,
                     const float* __restrict__ q_m,  const float* __restrict__ q_v)
{
    extern __shared__ char sm[];
    const uint32_t sb = smem_u32(sm);
    int*   rowoff = (int*)(sm + OFF_ROW);
    float* sInv   = (float*)(sm + OFF_INV);
    float* sSh    = (float*)(sm + OFF_SH);
    float* S      = (float*)(sm + OFF_STAGE);

    const int bx = blockIdx.x;
    int mode, n0, m0;
    if (bx < KB)      { mode = 0; n0 = (bx & 1) * 128;  m0 = (bx >> 1) * 128; }
    else if (bx < VB) { int i = bx - KB; mode = 1; n0 = (i & 3) * 128; m0 = (i >> 2) * 128; }
    else              { int i = bx - VB; mode = 2; n0 = (i & 1) * 128; m0 = (i >> 1) * 128; }

    const __half* Wf = (mode == 0) ? g_kwf : (mode == 1) ? g_vwf : g_qwf;

    const int tid = threadIdx.x;
    const int wid = tid >> 5;

    if (tid < 128) {
        int m = m0 + tid;
        int off;
        if (mode == 2) {
            int b = m / Qq, qq = m % Qq;
            int n = (qq / 7) * 28 + (qq % 7) * 2;
            off = (b * Nn + n) * 256;
        } else {
            off = m * 256;
        }
        rowoff[tid] = off;
        int jj = n0 + tid;
        int jo;
        const float *gg, *bb, *mm, *vv;
        if (mode == 0)      { jo = (jj >> 5) * 96 + (jj & 31);        gg = kv_g; bb = kv_b; mm = kv_m; vv = kv_v; }
        else if (mode == 1) { jo = (jj >> 6) * 96 + KDc + (jj & 63);  gg = kv_g; bb = kv_b; mm = kv_m; vv = kv_v; }
        else                { jo = jj;                                 gg = q_g;  bb = q_b;  mm = q_m;  vv = q_v;  }
        float inv = gg[jo] * rsqrtf(vv[jo] + EPSc);
        float sh  = bb[jo] - mm[jo] * inv;
        if (mode == 2) { inv *= SCALEc; sh *= SCALEc; }
        sInv[tid] = inv;
        sSh[tid]  = sh;
    }
    __syncthreads();

    // loader: 2 x 16B units per thread per matrix; unit u: row=u>>3, seg=u&7
    const int r0 = tid >> 3, seg8 = (tid & 7) * 8;
    const int r1 = r0 + 64;
    const int aoff0 = rowoff[r0] + seg8;
    const int aoff1 = rowoff[r1] + seg8;
    const int woff0 = (n0 + r0) * 256 + seg8;
    const int woff1 = (n0 + r1) * 256 + seg8;
    const uint32_t so0 = (uint32_t)(r0 * TSTRIDE + seg8) * 2;
    const uint32_t so1 = (uint32_t)(r1 * TSTRIDE + seg8) * 2;

    const int wm0 = (wid & 3) * 32;
    const int wn0 = (wid >> 2) * 32;

    wmma::fragment<wmma::accumulator, 16, 16, 16, float> acc[2][2];
#pragma unroll
    for (int i = 0; i < 2; i++)
#pragma unroll
        for (int j = 0; j < 2; j++) wmma::fill_fragment(acc[i][j], 0.0f);

    auto load1 = [&](int c, int stage) {
        const uint32_t base = sb + OFF_TILES + stage * STAGE_BYTES;
        const int k0 = c * 64;
        cp16(base + so0,              g_xh + aoff0 + k0);
        cp16(base + so1,              g_xh + aoff1 + k0);
        cp16(base + TILE_BYTES + so0, Wf + woff0 + k0);
        cp16(base + TILE_BYTES + so1, Wf + woff1 + k0);
        CP_COMMIT();
    };
    load1(0, 0);

#pragma unroll 1
    for (int c = 0; c < 4; c++) {
        CP_WAIT0();
        __syncthreads();                   // single barrier per chunk
        if (c + 1 < 4) load1(c + 1, (c + 1) & 1);
        char* st = sm + OFF_TILES + (c & 1) * STAGE_BYTES;
        __half* Ahs = (__half*)(st);
        __half* Wfs = (__half*)(st + TILE_BYTES);
#pragma unroll
        for (int kk = 0; kk < 64; kk += 16) {
#pragma unroll
            for (int j = 0; j < 2; j++) {
                wmma::fragment<wmma::matrix_b, 16, 16, 16, __half, wmma::col_major> bf;
                wmma::load_matrix_sync(bf, Wfs + (wn0 + j * 16) * TSTRIDE + kk, TSTRIDE);
#pragma unroll
                for (int i = 0; i < 2; i++) {
                    wmma::fragment<wmma::matrix_a, 16, 16, 16, __half, wmma::row_major> af;
                    wmma::load_matrix_sync(af, Ahs + (wm0 + i * 16) * TSTRIDE + kk, TSTRIDE);
                    wmma::mma_sync(acc[i][j], af, bf, acc[i][j]);
                }
            }
        }
    }
    __syncthreads();                       // all MMAs done before S overwrites tiles

#pragma unroll
    for (int i = 0; i < 2; i++)
#pragma unroll
        for (int j = 0; j < 2; j++)
            wmma::store_matrix_sync(S + (wm0 + i * 16) * SSTRIDE + wn0 + j * 16,
                                    acc[i][j], SSTRIDE, wmma::mem_row_major);
    __syncthreads();

    for (int idx = tid; idx < 8192; idx += 512) {
        int mrow = idx >> 6, pair = idx & 63, col = pair * 2;
        int jj = n0 + col;
        int m = m0 + mrow;
        float v0 = S[mrow * SSTRIDE + col]     * sInv[col]     + sSh[col];
        float v1 = S[mrow * SSTRIDE + col + 1] * sInv[col + 1] + sSh[col + 1];
        __half2 hv = __floats2half2_rn(v0, v1);
        if (mode == 0) {
            int h = jj >> 5, d = jj & 31;
            int b = m / Nn, n = m - b * Nn;
            *reinterpret_cast<__half2*>(g_kf + ((size_t)((b * Hh + h) * Nn + n)) * KDc + d) = hv;
        } else if (mode == 1) {
            int h = jj >> 6, d = jj & 63;
            int b = m / Nn, n = m - b * Nn;
            *reinterpret_cast<__half2*>(g_vf + ((size_t)((b * Hh + h) * Nn + n)) * VDc + d) = hv;
        } else {
            int h = jj >> 5, d = jj & 31;
            int b = m / Qq, qq = m - b * Qq;
            *reinterpret_cast<__half2*>(g_qf + ((size_t)((b * Hh + h) * Qq + qq)) * KDc + d) = hv;
        }
    }
}

// ---------------------------------------------------------------------------
// proj GEMM: single-term fp16, 512 threads, 32x32 warp tiles, K-chunk 64.
// ---------------------------------------------------------------------------
#define PGEMM_SMEM_BYTES GEMM_SMEM_BYTES

__global__ __launch_bounds__(512, 2)
void pgemm_kernel(const float* __restrict__ gg,
                  const float* __restrict__ bb,
                  const float* __restrict__ mm,
                  const float* __restrict__ vv,
                  float* __restrict__ Out)
{
    extern __shared__ char sm[];
    const uint32_t sb = smem_u32(sm);
    float* sSh  = (float*)(sm + OFF_SH);
    float* S    = (float*)(sm + OFF_STAGE);

    const int tid = threadIdx.x;
    const int wid = tid >> 5;
    const int m0 = blockIdx.y * 128;
    const int n0 = blockIdx.x * 128;

    if (tid < 128) {
        int jj = n0 + tid;
        float inv = gg[jj] * rsqrtf(vv[jj] + EPSc);
        sSh[tid]  = bb[jj] - mm[jj] * inv;
    }
    __syncthreads();

    const int r0 = tid >> 3, seg8 = (tid & 7) * 8;
    const int r1 = r0 + 64;
    const int aoff0 = (m0 + r0) * 512 + seg8;
    const int aoff1 = (m0 + r1) * 512 + seg8;
    const int woff0 = (n0 + r0) * 512 + seg8;
    const int woff1 = (n0 + r1) * 512 + seg8;
    const uint32_t so0 = (uint32_t)(r0 * TSTRIDE + seg8) * 2;
    const uint32_t so1 = (uint32_t)(r1 * TSTRIDE + seg8) * 2;

    const int wm0 = (wid & 3) * 32;
    const int wn0 = (wid >> 2) * 32;

    wmma::fragment<wmma::accumulator, 16, 16, 16, float> acc[2][2];
#pragma unroll
    for (int i = 0; i < 2; i++)
#pragma unroll
        for (int j = 0; j < 2; j++) wmma::fill_fragment(acc[i][j], 0.0f);

    auto load_chunk = [&](int c, int stage) {
        const uint32_t base = sb + OFF_TILES + stage * STAGE_BYTES;
        const int k0 = c * 64;
        cp16(base + so0,              g_af + aoff0 + k0);
        cp16(base + so1,              g_af + aoff1 + k0);
        cp16(base + TILE_BYTES + so0, g_pwf + woff0 + k0);
        cp16(base + TILE_BYTES + so1, g_pwf + woff1 + k0);
        CP_COMMIT();
    };

    load_chunk(0, 0);

#pragma unroll 1
    for (int c = 0; c < 8; c++) {
        CP_WAIT0();
        __syncthreads();
        if (c + 1 < 8) load_chunk(c + 1, (c + 1) & 1);

        char* st = sm + OFF_TILES + (c & 1) * STAGE_BYTES;
        __half* Afs = (__half*)(st);
        __half* Wfs = (__half*)(st + TILE_BYTES);

#pragma unroll
        for (int kk = 0; kk < 64; kk += 16) {
#pragma unroll
            for (int j = 0; j < 2; j++) {
                wmma::fragment<wmma::matrix_b, 16, 16, 16, __half, wmma::col_major> bf;
                wmma::load_matrix_sync(bf, Wfs + (wn0 + j * 16) * TSTRIDE + kk, TSTRIDE);
#pragma unroll
                for (int i = 0; i < 2; i++) {
                    wmma::fragment<wmma::matrix_a, 16, 16, 16, __half, wmma::row_major> af;
                    wmma::load_matrix_sync(af, Afs + (wm0 + i * 16) * TSTRIDE + kk, TSTRIDE);
                    wmma::mma_sync(acc[i][j], af, bf, acc[i][j]);
                }
            }
        }
    }
    __syncthreads();

#pragma unroll
    for (int i = 0; i < 2; i++)
#pragma unroll
        for (int j = 0; j < 2; j++)
            wmma::store_matrix_sync(S + (wm0 + i * 16) * SSTRIDE + wn0 + j * 16,
                                    acc[i][j], SSTRIDE, wmma::mem_row_major);
    __syncthreads();

    for (int idx = tid; idx < 4096; idx += 512) {
        int mrow = idx >> 5, col = (idx & 31) * 4;
        float4 o;
        o.x = S[mrow * SSTRIDE + col + 0] + sSh[col + 0];
        o.y = S[mrow * SSTRIDE + col + 1] + sSh[col + 1];
        o.z = S[mrow * SSTRIDE + col + 2] + sSh[col + 2];
        o.w = S[mrow * SSTRIDE + col + 3] + sSh[col + 3];
        *reinterpret_cast<float4*>(Out + (size_t)(m0 + mrow) * 384 + n0 + col) = o;
    }
}

// ---------------------------------------------------------------------------
// Attention (frozen from round 16): one block per (b,h), 512 threads, 75.8 KB.
// ---------------------------------------------------------------------------
#define AT_BIAS 0
#define AT_SCP  832
#define AT_QF   28480
#define AT_KF   33600
#define AT_VH   28480
#define AT_OUT  58432
#define ATTN_SMEM_BYTES 75840

__global__ __launch_bounds__(512, 2)
void attn_kernel(const float* __restrict__ attn_bias)
{
    extern __shared__ char smc[];
    const uint32_t sb = smem_u32(smc);
    float* bs  = (float*)(smc + AT_BIAS);
    __half* scP = (__half*)(smc + AT_SCP);   // [64][216]
    __half* qf  = (__half*)(smc + AT_QF);    // [64][40]
    __half* kf  = (__half*)(smc + AT_KF);    // [208][40]
    __half* Vh  = (__half*)(smc + AT_VH);    // [208][72]
    float*  Ot  = (float*)(smc + AT_OUT);    // [64][68]

    const int blk = blockIdx.x;
    const int h = blk & 7;
    const int tid = threadIdx.x;
    const int wid = tid >> 5, lane = tid & 31;

    {
        const uint4* qg = (const uint4*)(g_qf + (size_t)blk * (Qq * KDc));
        for (int i = tid; i < 196; i += 512)
            cp16(sb + AT_QF + (i >> 2) * 80 + (i & 3) * 16, qg + i);
        const uint4* kg = (const uint4*)(g_kf + (size_t)blk * (Nn * KDc));
        for (int i = tid; i < 784; i += 512)
            cp16(sb + AT_KF + (i >> 2) * 80 + (i & 3) * 16, kg + i);
        CP_COMMIT();
        uint4 z = {0u, 0u, 0u, 0u};
        for (int i = tid; i < 75; i += 512) {
            int row = 49 + i / 5, seg = i % 5;
            *(uint4*)(smc + AT_QF + row * 80 + seg * 16) = z;
        }
        for (int i = tid; i < 196; i += 512) bs[i] = attn_bias[h * Nn + i];
        CP_WAIT0();
    }
    __syncthreads();

    if (wid < 13) {
        const int n0 = wid * 16;
        wmma::fragment<wmma::accumulator, 16, 16, 16, __half> acc[4];
#pragma unroll
        for (int mt = 0; mt < 4; mt++) wmma::fill_fragment(acc[mt], __float2half(0.0f));
#pragma unroll
        for (int kk = 0; kk < 2; kk++) {
            wmma::fragment<wmma::matrix_b, 16, 16, 16, __half, wmma::col_major> bf;
            wmma::load_matrix_sync(bf, kf + n0 * 40 + kk * 16, 40);
#pragma unroll
            for (int mt = 0; mt < 4; mt++) {
                wmma::fragment<wmma::matrix_a, 16, 16, 16, __half, wmma::row_major> af;
                wmma::load_matrix_sync(af, qf + mt * 16 * 40 + kk * 16, 40);
                wmma::mma_sync(acc[mt], af, bf, acc[mt]);
            }
        }
#pragma unroll
        for (int mt = 0; mt < 4; mt++)
            wmma::store_matrix_sync(scP + mt * 16 * 216 + n0, acc[mt], 216, wmma::mem_row_major);
    }
    __syncthreads();

    {
        const uint4* vfg = (const uint4*)(g_vf + (size_t)blk * (Nn * VDc));
        for (int i = tid; i < 1568; i += 512)
            cp16(sb + AT_VH + (i >> 3) * 144 + (i & 7) * 16, vfg + i);
        CP_COMMIT();
        uint4 z = {0u, 0u, 0u, 0u};
        for (int i = tid; i < 108; i += 512) {
            int row = 196 + i / 9, seg = i % 9;
            *(uint4*)(smc + AT_VH + row * 144 + seg * 16) = z;
        }
    }

    for (int row = wid; row < Qq; row += 16) {
        int qi2 = 2 * (row / 7), qj2 = 2 * (row % 7);
        float v[7];
        float mx = -1e30f;
#pragma unroll
        for (int t = 0; t < 7; t++) {
            int n = lane + t * 32;
            if (n < Nn) {
                int ki = n / 14, kj = n - ki * 14;
                float val = __half2float(scP[row * 216 + n]) + bs[abs(qi2 - ki) * 14 + abs(qj2 - kj)];
                v[t] = val;
                mx = fmaxf(mx, val);
            }
        }
#pragma unroll
        for (int o = 16; o > 0; o >>= 1)
            mx = fmaxf(mx, __shfl_xor_sync(0xffffffffu, mx, o));
        float sum = 0.0f;
#pragma unroll
        for (int t = 0; t < 7; t++) {
            int n = lane + t * 32;
            if (n < Nn) {
                float e = __expf(v[t] - mx);
                v[t] = e;
                sum += e;
            }
        }
#pragma unroll
        for (int o = 16; o > 0; o >>= 1)
            sum += __shfl_xor_sync(0xffffffffu, sum, o);
        float rinv = 1.0f / sum;
#pragma unroll
        for (int t = 0; t < 7; t++) {
            int n = lane + t * 32;
            if (n < Nn)        scP[row * 216 + n] = __float2half_rn(v[t] * rinv);
            else if (n < 208)  scP[row * 216 + n] = __float2half_rn(0.0f);
        }
    }
    CP_WAIT0();
    __syncthreads();

    {
        const int mi = wid >> 2, ni = wid & 3;
        wmma::fragment<wmma::accumulator, 16, 16, 16, float> acc;
        wmma::fill_fragment(acc, 0.0f);
#pragma unroll
        for (int kk = 0; kk < 13; kk++) {
            wmma::fragment<wmma::matrix_a, 16, 16, 16, __half, wmma::row_major> pf;
            wmma::fragment<wmma::matrix_b, 16, 16, 16, __half, wmma::row_major> vf;
            wmma::load_matrix_sync(pf, scP + mi * 16 * 216 + kk * 16, 216);
            wmma::load_matrix_sync(vf, Vh + kk * 16 * 72 + ni * 16, 72);
            wmma::mma_sync(acc, pf, vf, acc);
        }
        wmma::store_matrix_sync(Ot + mi * 16 * 68 + ni * 16, acc, 68, wmma::mem_row_major);
    }
    __syncthreads();

    {
        const int b = blk >> 3;
        for (int i = tid; i < 1568; i += 512) {
            int qr = i >> 5, vd = (i & 31) * 2;
            float t0 = Ot[qr * 68 + vd];
            float t1 = Ot[qr * 68 + vd + 1];
            float o0 = t0 * fminf(fmaxf(t0 + 3.0f, 0.0f), 6.0f) * (1.0f / 6.0f);
            float o1 = t1 * fminf(fmaxf(t1 + 3.0f, 0.0f), 6.0f) * (1.0f / 6.0f);
            size_t off = ((size_t)(b * Qq + qr)) * 512 + h * VDc + vd;
            *reinterpret_cast<__half2*>(g_af + off) = __floats2half2_rn(o0, o1);
        }
    }
}

// ---------------------------------------------------------------------------
extern "C" void kernel_launch(void* const* d_in, const int* in_sizes, int n_in,
                              void* d_out, int out_size)
{
    const float* x      = (const float*)d_in[0];
    const float* kv_w   = (const float*)d_in[1];
    const float* kv_g   = (const float*)d_in[2];
    const float* kv_b   = (const float*)d_in[3];
    const float* kv_m   = (const float*)d_in[4];
    const float* kv_v   = (const float*)d_in[5];
    const float* q_w    = (const float*)d_in[6];
    const float* q_g    = (const float*)d_in[7];
    const float* q_b    = (const float*)d_in[8];
    const float* q_m    = (const float*)d_in[9];
    const float* q_v    = (const float*)d_in[10];
    const float* proj_w = (const float*)d_in[11];
    const float* proj_g = (const float*)d_in[12];
    const float* proj_b = (const float*)d_in[13];
    const float* proj_m = (const float*)d_in[14];
    const float* proj_v = (const float*)d_in[15];
    const float* attn_bias = (const float*)d_in[16];
    float* out = (float*)d_out;

    split_all_kernel<<<(NX + NW1 + NW2 + NW3 + 255) / 256, 256>>>(
        x, kv_w, q_w, proj_w, proj_g, proj_v);

    cudaFuncSetAttribute(kvq_gemm_kernel, cudaFuncAttributeMaxDynamicSharedMemorySize, GEMM_SMEM_BYTES);
    cudaFuncSetAttribute(pgemm_kernel, cudaFuncAttributeMaxDynamicSharedMemorySize, PGEMM_SMEM_BYTES);
    cudaFuncSetAttribute(attn_kernel, cudaFuncAttributeMaxDynamicSharedMemorySize, ATTN_SMEM_BYTES);

    kvq_gemm_kernel<<<TOTAL_B, 512, GEMM_SMEM_BYTES>>>(
        kv_g, kv_b, kv_m, kv_v, q_g, q_b, q_m, q_v);

    attn_kernel<<<Bc * Hh, 512, ATTN_SMEM_BYTES>>>(attn_bias);

    pgemm_kernel<<<dim3(3, 98), 512, PGEMM_SMEM_BYTES>>>(proj_g, proj_b, proj_m, proj_v, out);
}